// round 3
// baseline (speedup 1.0000x reference)
#include <cuda_runtime.h>
#include <math.h>

#define BB    8
#define NHH   12
#define HID   768
#define HD    64
#define SS    1024
#define QQ    2048
#define EDGE  32
#define KPOOL 16
#define PDIM  17
#define TQ    128
#define TS    128
#define QCHUNKS (QQ/TQ)     /* 16 */
#define BH    (BB*NHH)      /* 96 */
#define PADK  132

// ---------------- scratch (static device arrays; no allocation) ----------------
__device__ float g_partial[(size_t)BH * QCHUNKS * SS];   // per-chunk column-sum partials
__device__ int   g_row[BH];
__device__ int   g_col[BH];
__device__ float g_up[(size_t)BB * SS * HID];            // pixel-shuffled upsample ("out" pre-W_in)

// =========================================================================
// Kernel A: for each (b,h,q-chunk): two-pass softmax column sums.
//   pass1: l_q = sum_s exp2(z2_qs)    (z2 = q.k * log2(e)/8)
//   pass2: colsum[s] += sum_q exp2(z2_qs)/l_q
// 128x128 logits tile, 8x8 microtile, fp32 FFMA.
// =========================================================================
__global__ __launch_bounds__(256, 2)
void attn_colsum_kernel(const float* __restrict__ img, const float* __restrict__ txt)
{
    extern __shared__ float sm[];
    float* QsT  = sm;                       // [64][PADK]
    float* KsT  = sm + 64 * PADK;           // [64][PADK]
    float* red  = sm + 2 * 64 * PADK;       // 2048 floats (reused)
    float* linv = red + 2048;               // 128 floats

    const int chunk = blockIdx.x, h = blockIdx.y, b = blockIdx.z;
    const int tid = threadIdx.x;
    const int ty = tid >> 4, tx = tid & 15;
    const float SCALE = 0.18033688011112042f;   // log2(e)/8

    // ---- load Q tile (transposed, pre-scaled) ----
    {
        const float* qbase = txt + ((size_t)b * QQ + (size_t)chunk * TQ) * HID + h * HD;
        #pragma unroll
        for (int it = 0; it < 8; it++) {
            int idx = tid + it * 256;
            int r = idx >> 4, seg = idx & 15;
            float4 v = __ldg((const float4*)(qbase + (size_t)r * HID) + seg);
            int d = seg * 4;
            QsT[(d + 0) * PADK + r] = v.x * SCALE;
            QsT[(d + 1) * PADK + r] = v.y * SCALE;
            QsT[(d + 2) * PADK + r] = v.z * SCALE;
            QsT[(d + 3) * PADK + r] = v.w * SCALE;
        }
    }
    const float* kroot = img + (size_t)b * SS * HID + h * HD;

    float rs[8];
    #pragma unroll
    for (int i = 0; i < 8; i++) rs[i] = 0.f;

    // -------------------- PASS 1: row sum of exp --------------------
    for (int st = 0; st < SS / TS; st++) {
        __syncthreads();
        #pragma unroll
        for (int it = 0; it < 8; it++) {
            int idx = tid + it * 256;
            int r = idx >> 4, seg = idx & 15;
            float4 v = __ldg((const float4*)(kroot + (size_t)(st * TS + r) * HID) + seg);
            int d = seg * 4;
            KsT[(d + 0) * PADK + r] = v.x;
            KsT[(d + 1) * PADK + r] = v.y;
            KsT[(d + 2) * PADK + r] = v.z;
            KsT[(d + 3) * PADK + r] = v.w;
        }
        __syncthreads();

        float acc[8][8];
        #pragma unroll
        for (int i = 0; i < 8; i++)
            #pragma unroll
            for (int j = 0; j < 8; j++) acc[i][j] = 0.f;

        #pragma unroll 4
        for (int d = 0; d < HD; d++) {
            float4 a0 = *(const float4*)&QsT[d * PADK + ty * 8];
            float4 a1 = *(const float4*)&QsT[d * PADK + ty * 8 + 4];
            float4 b0 = *(const float4*)&KsT[d * PADK + tx * 8];
            float4 b1 = *(const float4*)&KsT[d * PADK + tx * 8 + 4];
            float av[8] = {a0.x, a0.y, a0.z, a0.w, a1.x, a1.y, a1.z, a1.w};
            float bv[8] = {b0.x, b0.y, b0.z, b0.w, b1.x, b1.y, b1.z, b1.w};
            #pragma unroll
            for (int i = 0; i < 8; i++)
                #pragma unroll
                for (int j = 0; j < 8; j++) acc[i][j] += av[i] * bv[j];
        }
        #pragma unroll
        for (int i = 0; i < 8; i++) {
            float s0 = 0.f;
            #pragma unroll
            for (int j = 0; j < 8; j++) s0 += exp2f(acc[i][j]);
            rs[i] += s0;
        }
    }

    __syncthreads();
    #pragma unroll
    for (int i = 0; i < 8; i++) red[(ty * 8 + i) * 16 + tx] = rs[i];
    __syncthreads();
    if (tid < 128) {
        float l = 0.f;
        #pragma unroll
        for (int x = 0; x < 16; x++) l += red[tid * 16 + x];
        linv[tid] = 1.0f / l;
    }
    __syncthreads();

    float lvv[8];
    #pragma unroll
    for (int i = 0; i < 8; i++) lvv[i] = linv[ty * 8 + i];

    const int bh = b * NHH + h;
    float* pbase = g_partial + ((size_t)bh * QCHUNKS + chunk) * SS;

    // -------------------- PASS 2: column sums --------------------
    for (int st = 0; st < SS / TS; st++) {
        __syncthreads();
        #pragma unroll
        for (int it = 0; it < 8; it++) {
            int idx = tid + it * 256;
            int r = idx >> 4, seg = idx & 15;
            float4 v = __ldg((const float4*)(kroot + (size_t)(st * TS + r) * HID) + seg);
            int d = seg * 4;
            KsT[(d + 0) * PADK + r] = v.x;
            KsT[(d + 1) * PADK + r] = v.y;
            KsT[(d + 2) * PADK + r] = v.z;
            KsT[(d + 3) * PADK + r] = v.w;
        }
        __syncthreads();

        float acc[8][8];
        #pragma unroll
        for (int i = 0; i < 8; i++)
            #pragma unroll
            for (int j = 0; j < 8; j++) acc[i][j] = 0.f;

        #pragma unroll 4
        for (int d = 0; d < HD; d++) {
            float4 a0 = *(const float4*)&QsT[d * PADK + ty * 8];
            float4 a1 = *(const float4*)&QsT[d * PADK + ty * 8 + 4];
            float4 b0 = *(const float4*)&KsT[d * PADK + tx * 8];
            float4 b1 = *(const float4*)&KsT[d * PADK + tx * 8 + 4];
            float av[8] = {a0.x, a0.y, a0.z, a0.w, a1.x, a1.y, a1.z, a1.w};
            float bv[8] = {b0.x, b0.y, b0.z, b0.w, b1.x, b1.y, b1.z, b1.w};
            #pragma unroll
            for (int i = 0; i < 8; i++)
                #pragma unroll
                for (int j = 0; j < 8; j++) acc[i][j] += av[i] * bv[j];
        }

        float colp[8];
        #pragma unroll
        for (int j = 0; j < 8; j++) colp[j] = 0.f;
        #pragma unroll
        for (int i = 0; i < 8; i++) {
            float li = lvv[i];
            #pragma unroll
            for (int j = 0; j < 8; j++) colp[j] += exp2f(acc[i][j]) * li;
        }
        *(float4*)&red[ty * 128 + tx * 8]     = make_float4(colp[0], colp[1], colp[2], colp[3]);
        *(float4*)&red[ty * 128 + tx * 8 + 4] = make_float4(colp[4], colp[5], colp[6], colp[7]);
        __syncthreads();
        if (tid < 128) {
            float c = 0.f;
            #pragma unroll
            for (int y = 0; y < 16; y++) c += red[y * 128 + tid];
            pbase[st * TS + tid] = c;
        }
    }
}

// =========================================================================
// Kernel B: reduce partials -> saliency map, 16x16 mean-pool (sums; argmax
// invariant to /256), argmax with first-index tie-break (matches jnp.argmax).
// =========================================================================
__global__ void pool_argmax_kernel()
{
    __shared__ float attn[SS];
    __shared__ float hsum[EDGE * PDIM];
    __shared__ float pooled[PDIM * PDIM];
    const int bh = blockIdx.x;
    const int tid = threadIdx.x;

    for (int s = tid; s < SS; s += 256) {
        float v = 0.f;
        #pragma unroll
        for (int c = 0; c < QCHUNKS; c++)
            v += g_partial[((size_t)bh * QCHUNKS + c) * SS + s];
        attn[s] = v;
    }
    __syncthreads();
    for (int t = tid; t < EDGE * PDIM; t += 256) {
        int r = t / PDIM, c = t % PDIM;
        float v = 0.f;
        #pragma unroll
        for (int j = 0; j < KPOOL; j++) v += attn[r * EDGE + c + j];
        hsum[t] = v;
    }
    __syncthreads();
    for (int t = tid; t < PDIM * PDIM; t += 256) {
        int r0 = t / PDIM, c = t % PDIM;
        float v = 0.f;
        #pragma unroll
        for (int r = 0; r < KPOOL; r++) v += hsum[(r0 + r) * PDIM + c];
        pooled[t] = v;
    }
    __syncthreads();
    if (tid == 0) {
        float best = -1e30f; int bi = 0;
        for (int t = 0; t < PDIM * PDIM; t++) {
            if (pooled[t] > best) { best = pooled[t]; bi = t; }
        }
        g_row[bh] = bi / PDIM;
        g_col[bh] = bi % PDIM;
    }
}

// =========================================================================
// Kernel C: gather argmax 16x16 region, @ W_up, pixel-shuffle into g_up.
// One CTA per (b,h); thread = one (r2,c2) position; region held in registers.
// =========================================================================
__global__ __launch_bounds__(256)
void upsample_kernel(const float* __restrict__ img, const float* __restrict__ Wup)
{
    extern __shared__ float WsT[];  // [256][68] transposed W_up
    const int bh = blockIdx.x;
    const int b = bh / NHH, h = bh % NHH;
    const int tid = threadIdx.x;

    for (int i = tid; i < HD * 256; i += 256) {
        int k = i >> 8, c = i & 255;
        WsT[c * 68 + k] = Wup[i];
    }
    const int row = g_row[bh], col = g_col[bh];
    __syncthreads();

    const int r2 = tid >> 4, c2 = tid & 15;
    const float* rp = img + ((size_t)b * SS + (size_t)(row + r2) * EDGE + (col + c2)) * HID + h * HD;
    float reg[HD];
    #pragma unroll
    for (int k4 = 0; k4 < 16; k4++) {
        float4 v = __ldg((const float4*)rp + k4);
        reg[k4 * 4 + 0] = v.x; reg[k4 * 4 + 1] = v.y;
        reg[k4 * 4 + 2] = v.z; reg[k4 * 4 + 3] = v.w;
    }
    float* outbase = g_up + (size_t)b * SS * HID + h * HD;
    for (int co = 0; co < 256; co++) {
        float acc = 0.f;
        const float4* w = (const float4*)&WsT[co * 68];
        #pragma unroll
        for (int k4 = 0; k4 < 16; k4++) {
            float4 wv = w[k4];
            acc += reg[k4 * 4 + 0] * wv.x + reg[k4 * 4 + 1] * wv.y
                 + reg[k4 * 4 + 2] * wv.z + reg[k4 * 4 + 3] * wv.w;
        }
        int dr = co >> 7, dc = (co >> 6) & 1, d = co & 63;
        int pos = (2 * r2 + dr) * EDGE + (2 * c2 + dc);
        outbase[(size_t)pos * HID + d] = acc;
    }
}

// =========================================================================
// Kernel D: out = residual + gelu_exact(g_up @ W_in).  128x128x16 SGEMM tile.
// =========================================================================
__device__ __forceinline__ float gelu_exact(float x)
{
    return 0.5f * x * (1.0f + erff(x * 0.70710678118654752440f));
}

__global__ __launch_bounds__(256, 2)
void gemm_gelu_res_kernel(const float* __restrict__ Win, const float* __restrict__ img,
                          float* __restrict__ out)
{
    __shared__ float AsT[16 * PADK];  // [16][132] (k x row)
    __shared__ float Bs[16 * 128];    // [16][128] (k x col)
    const int ct = blockIdx.x, rt = blockIdx.y, b = blockIdx.z;
    const int tid = threadIdx.x;
    const int ty = tid >> 4, tx = tid & 15;
    const int row0 = rt * 128, col0 = ct * 128;
    const float* A = g_up + ((size_t)b * SS + row0) * HID;

    float acc[8][8];
    #pragma unroll
    for (int i = 0; i < 8; i++)
        #pragma unroll
        for (int j = 0; j < 8; j++) acc[i][j] = 0.f;

    for (int kb = 0; kb < HID; kb += 16) {
        __syncthreads();
        #pragma unroll
        for (int it = 0; it < 2; it++) {
            int idx = tid + it * 256;
            int r = idx >> 2, q4 = idx & 3;
            float4 v = *(const float4*)(A + (size_t)r * HID + kb + q4 * 4);
            int d = q4 * 4;
            AsT[(d + 0) * PADK + r] = v.x;
            AsT[(d + 1) * PADK + r] = v.y;
            AsT[(d + 2) * PADK + r] = v.z;
            AsT[(d + 3) * PADK + r] = v.w;
        }
        #pragma unroll
        for (int it = 0; it < 2; it++) {
            int idx = tid + it * 256;
            int k = idx >> 5, c4 = idx & 31;
            float4 v = __ldg((const float4*)(Win + (size_t)(kb + k) * HID + col0 + c4 * 4));
            *(float4*)&Bs[k * 128 + c4 * 4] = v;
        }
        __syncthreads();
        #pragma unroll
        for (int kk = 0; kk < 16; kk++) {
            float4 a0 = *(const float4*)&AsT[kk * PADK + ty * 8];
            float4 a1 = *(const float4*)&AsT[kk * PADK + ty * 8 + 4];
            float4 b0 = *(const float4*)&Bs[kk * 128 + tx * 8];
            float4 b1 = *(const float4*)&Bs[kk * 128 + tx * 8 + 4];
            float av[8] = {a0.x, a0.y, a0.z, a0.w, a1.x, a1.y, a1.z, a1.w};
            float bv[8] = {b0.x, b0.y, b0.z, b0.w, b1.x, b1.y, b1.z, b1.w};
            #pragma unroll
            for (int i = 0; i < 8; i++)
                #pragma unroll
                for (int j = 0; j < 8; j++) acc[i][j] += av[i] * bv[j];
        }
    }

    #pragma unroll
    for (int i = 0; i < 8; i++) {
        int row = row0 + ty * 8 + i;
        const float4* res = (const float4*)(img + ((size_t)b * SS + row) * HID + col0 + tx * 8);
        float4 r0 = res[0], r1 = res[1];
        float4 o0, o1;
        o0.x = r0.x + gelu_exact(acc[i][0]);
        o0.y = r0.y + gelu_exact(acc[i][1]);
        o0.z = r0.z + gelu_exact(acc[i][2]);
        o0.w = r0.w + gelu_exact(acc[i][3]);
        o1.x = r1.x + gelu_exact(acc[i][4]);
        o1.y = r1.y + gelu_exact(acc[i][5]);
        o1.z = r1.z + gelu_exact(acc[i][6]);
        o1.w = r1.w + gelu_exact(acc[i][7]);
        float4* dst = (float4*)(out + ((size_t)b * SS + row) * HID + col0 + tx * 8);
        dst[0] = o0;
        dst[1] = o1;
    }
}

// =========================================================================
extern "C" void kernel_launch(void* const* d_in, const int* in_sizes, int n_in,
                              void* d_out, int out_size)
{
    const float* img = (const float*)d_in[0];   // [8,1024,768]
    const float* txt = (const float*)d_in[1];   // [8,2048,768]
    const float* Win = (const float*)d_in[2];   // [768,768]
    const float* Wup = (const float*)d_in[3];   // [64,256]
    float* out = (float*)d_out;                 // [8,1024,768]

    const int smemA = (2 * 64 * PADK + 2048 + 128) * (int)sizeof(float);   // 76288
    const int smemC = 256 * 68 * (int)sizeof(float);                        // 69632
    cudaFuncSetAttribute(attn_colsum_kernel, cudaFuncAttributeMaxDynamicSharedMemorySize, smemA);
    cudaFuncSetAttribute(upsample_kernel,    cudaFuncAttributeMaxDynamicSharedMemorySize, smemC);

    attn_colsum_kernel<<<dim3(QCHUNKS, NHH, BB), 256, smemA>>>(img, txt);
    pool_argmax_kernel<<<BH, 256>>>();
    upsample_kernel<<<BH, 256, smemC>>>(img, Wup);
    gemm_gelu_res_kernel<<<dim3(HID / 128, SS / 128, BB), 256>>>(Win, img, out);
}

// round 7
// speedup vs baseline: 1.3161x; 1.3161x over previous
#include <cuda_runtime.h>
#include <math.h>

#define BB    8
#define NHH   12
#define HID   768
#define HD    64
#define SS    1024
#define QQ    2048
#define EDGE  32
#define KPOOL 16
#define PDIM  17
#define TQ    128
#define TS    128
#define QCHUNKS (QQ/TQ)     /* 16 */
#define BH    (BB*NHH)      /* 96 */
#define PADK  132

// ---------------- scratch (static device arrays; no allocation) ----------------
__device__ float g_P[(size_t)BH * QQ * SS];     // unnormalized exp(z)  (805 MB)
__device__ float g_linv[(size_t)BH * QQ];       // 1 / rowsum
__device__ float g_colsum[(size_t)BH * SS];     // softmax column sums
__device__ int   g_row[BH];
__device__ int   g_col[BH];
__device__ float g_up[(size_t)BB * SS * HID];   // pixel-shuffled upsample ("out" pre-W_in)

// =========================================================================
// Kernel A1: single QK^T pass per (b,h,q-chunk).
//   computes z tile, e = exp2(z*log2e/8); stores e to g_P; row-sums -> g_linv.
// 128x128 logits tile, 8x8 microtile, fp32 FFMA (at FFMA roofline).
// =========================================================================
__global__ __launch_bounds__(256, 2)
void attn_exp_kernel(const float* __restrict__ img, const float* __restrict__ txt)
{
    extern __shared__ float sm[];
    float* QsT  = sm;                       // [64][PADK]
    float* KsT  = sm + 64 * PADK;           // [64][PADK]
    float* red  = sm + 2 * 64 * PADK;       // 2048 floats

    const int chunk = blockIdx.x, h = blockIdx.y, b = blockIdx.z;
    const int tid = threadIdx.x;
    const int ty = tid >> 4, tx = tid & 15;
    const float SCALE = 0.18033688011112042f;   // log2(e)/8

    // ---- load Q tile (transposed, pre-scaled) ----
    {
        const float* qbase = txt + ((size_t)b * QQ + (size_t)chunk * TQ) * HID + h * HD;
        #pragma unroll
        for (int it = 0; it < 8; it++) {
            int idx = tid + it * 256;
            int r = idx >> 4, seg = idx & 15;
            float4 v = __ldg((const float4*)(qbase + (size_t)r * HID) + seg);
            int d = seg * 4;
            QsT[(d + 0) * PADK + r] = v.x * SCALE;
            QsT[(d + 1) * PADK + r] = v.y * SCALE;
            QsT[(d + 2) * PADK + r] = v.z * SCALE;
            QsT[(d + 3) * PADK + r] = v.w * SCALE;
        }
    }
    const float* kroot = img + (size_t)b * SS * HID + h * HD;
    const int bh = b * NHH + h;
    float* pbase = g_P + ((size_t)bh * QQ + (size_t)chunk * TQ) * SS;

    float rs[8];
    #pragma unroll
    for (int i = 0; i < 8; i++) rs[i] = 0.f;

    for (int st = 0; st < SS / TS; st++) {
        __syncthreads();
        #pragma unroll
        for (int it = 0; it < 8; it++) {
            int idx = tid + it * 256;
            int r = idx >> 4, seg = idx & 15;
            float4 v = __ldg((const float4*)(kroot + (size_t)(st * TS + r) * HID) + seg);
            int d = seg * 4;
            KsT[(d + 0) * PADK + r] = v.x;
            KsT[(d + 1) * PADK + r] = v.y;
            KsT[(d + 2) * PADK + r] = v.z;
            KsT[(d + 3) * PADK + r] = v.w;
        }
        __syncthreads();

        float acc[8][8];
        #pragma unroll
        for (int i = 0; i < 8; i++)
            #pragma unroll
            for (int j = 0; j < 8; j++) acc[i][j] = 0.f;

        #pragma unroll 4
        for (int d = 0; d < HD; d++) {
            float4 a0 = *(const float4*)&QsT[d * PADK + ty * 8];
            float4 a1 = *(const float4*)&QsT[d * PADK + ty * 8 + 4];
            float4 b0 = *(const float4*)&KsT[d * PADK + tx * 8];
            float4 b1 = *(const float4*)&KsT[d * PADK + tx * 8 + 4];
            float av[8] = {a0.x, a0.y, a0.z, a0.w, a1.x, a1.y, a1.z, a1.w};
            float bv[8] = {b0.x, b0.y, b0.z, b0.w, b1.x, b1.y, b1.z, b1.w};
            #pragma unroll
            for (int i = 0; i < 8; i++)
                #pragma unroll
                for (int j = 0; j < 8; j++) acc[i][j] += av[i] * bv[j];
        }

        // exp, row-sum accumulate, store unnormalized exp to g_P
        #pragma unroll
        for (int i = 0; i < 8; i++) {
            float e[8];
            #pragma unroll
            for (int j = 0; j < 8; j++) e[j] = exp2f(acc[i][j]);
            float s0 = 0.f;
            #pragma unroll
            for (int j = 0; j < 8; j++) s0 += e[j];
            rs[i] += s0;
            float* pr = pbase + (size_t)(ty * 8 + i) * SS + st * TS + tx * 8;
            *(float4*)(pr)     = make_float4(e[0], e[1], e[2], e[3]);
            *(float4*)(pr + 4) = make_float4(e[4], e[5], e[6], e[7]);
        }
    }

    // row-sum reduction across the 16 tx owners of each row
    __syncthreads();
    #pragma unroll
    for (int i = 0; i < 8; i++) red[(ty * 8 + i) * 16 + tx] = rs[i];
    __syncthreads();
    if (tid < 128) {
        float l = 0.f;
        #pragma unroll
        for (int x = 0; x < 16; x++) l += red[tid * 16 + x];
        g_linv[(size_t)bh * QQ + chunk * TQ + tid] = 1.0f / l;
    }
}

// =========================================================================
// Kernel A2: memory-bound column reduce: colsum[s] = sum_q P[q][s]*linv[q].
// One thread per column s; coalesced row reads; 4 independent accumulators.
// =========================================================================
__global__ __launch_bounds__(256)
void colsum_kernel()
{
    __shared__ float sl[QQ];   // 8 KB of linv
    const int bh = blockIdx.y;
    const int s = blockIdx.x * 256 + threadIdx.x;

    for (int i = threadIdx.x; i < QQ; i += 256)
        sl[i] = g_linv[(size_t)bh * QQ + i];
    __syncthreads();

    const float* P = g_P + (size_t)bh * QQ * SS + s;
    float a0 = 0.f, a1 = 0.f, a2 = 0.f, a3 = 0.f;
    #pragma unroll 4
    for (int q = 0; q < QQ; q += 4) {
        a0 += __ldg(P + (size_t)(q + 0) * SS) * sl[q + 0];
        a1 += __ldg(P + (size_t)(q + 1) * SS) * sl[q + 1];
        a2 += __ldg(P + (size_t)(q + 2) * SS) * sl[q + 2];
        a3 += __ldg(P + (size_t)(q + 3) * SS) * sl[q + 3];
    }
    g_colsum[(size_t)bh * SS + s] = (a0 + a1) + (a2 + a3);
}

// =========================================================================
// Kernel B: 16x16 mean-pool (sums; argmax invariant to /256), argmax with
// first-index tie-break (matches jnp.argmax).
// =========================================================================
__global__ void pool_argmax_kernel()
{
    __shared__ float attn[SS];
    __shared__ float hsum[EDGE * PDIM];
    __shared__ float pooled[PDIM * PDIM];
    const int bh = blockIdx.x;
    const int tid = threadIdx.x;

    for (int s = tid; s < SS; s += 256)
        attn[s] = g_colsum[(size_t)bh * SS + s];
    __syncthreads();
    for (int t = tid; t < EDGE * PDIM; t += 256) {
        int r = t / PDIM, c = t % PDIM;
        float v = 0.f;
        #pragma unroll
        for (int j = 0; j < KPOOL; j++) v += attn[r * EDGE + c + j];
        hsum[t] = v;
    }
    __syncthreads();
    for (int t = tid; t < PDIM * PDIM; t += 256) {
        int r0 = t / PDIM, c = t % PDIM;
        float v = 0.f;
        #pragma unroll
        for (int r = 0; r < KPOOL; r++) v += hsum[(r0 + r) * PDIM + c];
        pooled[t] = v;
    }
    __syncthreads();
    if (tid == 0) {
        float best = -1e30f; int bi = 0;
        for (int t = 0; t < PDIM * PDIM; t++) {
            if (pooled[t] > best) { best = pooled[t]; bi = t; }
        }
        g_row[bh] = bi / PDIM;
        g_col[bh] = bi % PDIM;
    }
}

// =========================================================================
// Kernel C: gather argmax 16x16 region, @ W_up, pixel-shuffle into g_up.
// =========================================================================
__global__ __launch_bounds__(256)
void upsample_kernel(const float* __restrict__ img, const float* __restrict__ Wup)
{
    extern __shared__ float WsT[];  // [256][68] transposed W_up
    const int bh = blockIdx.x;
    const int b = bh / NHH, h = bh % NHH;
    const int tid = threadIdx.x;

    for (int i = tid; i < HD * 256; i += 256) {
        int k = i >> 8, c = i & 255;
        WsT[c * 68 + k] = Wup[i];
    }
    const int row = g_row[bh], col = g_col[bh];
    __syncthreads();

    const int r2 = tid >> 4, c2 = tid & 15;
    const float* rp = img + ((size_t)b * SS + (size_t)(row + r2) * EDGE + (col + c2)) * HID + h * HD;
    float reg[HD];
    #pragma unroll
    for (int k4 = 0; k4 < 16; k4++) {
        float4 v = __ldg((const float4*)rp + k4);
        reg[k4 * 4 + 0] = v.x; reg[k4 * 4 + 1] = v.y;
        reg[k4 * 4 + 2] = v.z; reg[k4 * 4 + 3] = v.w;
    }
    float* outbase = g_up + (size_t)b * SS * HID + h * HD;
    for (int co = 0; co < 256; co++) {
        float acc = 0.f;
        const float4* w = (const float4*)&WsT[co * 68];
        #pragma unroll
        for (int k4 = 0; k4 < 16; k4++) {
            float4 wv = w[k4];
            acc += reg[k4 * 4 + 0] * wv.x + reg[k4 * 4 + 1] * wv.y
                 + reg[k4 * 4 + 2] * wv.z + reg[k4 * 4 + 3] * wv.w;
        }
        int dr = co >> 7, dc = (co >> 6) & 1, d = co & 63;
        int pos = (2 * r2 + dr) * EDGE + (2 * c2 + dc);
        outbase[(size_t)pos * HID + d] = acc;
    }
}

// =========================================================================
// Kernel D: out = residual + gelu_exact(g_up @ W_in).  128x128x16 SGEMM tile.
// =========================================================================
__device__ __forceinline__ float gelu_exact(float x)
{
    return 0.5f * x * (1.0f + erff(x * 0.70710678118654752440f));
}

__global__ __launch_bounds__(256, 2)
void gemm_gelu_res_kernel(const float* __restrict__ Win, const float* __restrict__ img,
                          float* __restrict__ out)
{
    __shared__ float AsT[16 * PADK];  // [16][132] (k x row)
    __shared__ float Bs[16 * 128];    // [16][128] (k x col)
    const int ct = blockIdx.x, rt = blockIdx.y, b = blockIdx.z;
    const int tid = threadIdx.x;
    const int ty = tid >> 4, tx = tid & 15;
    const int row0 = rt * 128, col0 = ct * 128;
    const float* A = g_up + ((size_t)b * SS + row0) * HID;

    float acc[8][8];
    #pragma unroll
    for (int i = 0; i < 8; i++)
        #pragma unroll
        for (int j = 0; j < 8; j++) acc[i][j] = 0.f;

    for (int kb = 0; kb < HID; kb += 16) {
        __syncthreads();
        #pragma unroll
        for (int it = 0; it < 2; it++) {
            int idx = tid + it * 256;
            int r = idx >> 2, q4 = idx & 3;
            float4 v = *(const float4*)(A + (size_t)r * HID + kb + q4 * 4);
            int d = q4 * 4;
            AsT[(d + 0) * PADK + r] = v.x;
            AsT[(d + 1) * PADK + r] = v.y;
            AsT[(d + 2) * PADK + r] = v.z;
            AsT[(d + 3) * PADK + r] = v.w;
        }
        #pragma unroll
        for (int it = 0; it < 2; it++) {
            int idx = tid + it * 256;
            int k = idx >> 5, c4 = idx & 31;
            float4 v = __ldg((const float4*)(Win + (size_t)(kb + k) * HID + col0 + c4 * 4));
            *(float4*)&Bs[k * 128 + c4 * 4] = v;
        }
        __syncthreads();
        #pragma unroll
        for (int kk = 0; kk < 16; kk++) {
            float4 a0 = *(const float4*)&AsT[kk * PADK + ty * 8];
            float4 a1 = *(const float4*)&AsT[kk * PADK + ty * 8 + 4];
            float4 b0 = *(const float4*)&Bs[kk * 128 + tx * 8];
            float4 b1 = *(const float4*)&Bs[kk * 128 + tx * 8 + 4];
            float av[8] = {a0.x, a0.y, a0.z, a0.w, a1.x, a1.y, a1.z, a1.w};
            float bv[8] = {b0.x, b0.y, b0.z, b0.w, b1.x, b1.y, b1.z, b1.w};
            #pragma unroll
            for (int i = 0; i < 8; i++)
                #pragma unroll
                for (int j = 0; j < 8; j++) acc[i][j] += av[i] * bv[j];
        }
    }

    #pragma unroll
    for (int i = 0; i < 8; i++) {
        int row = row0 + ty * 8 + i;
        const float4* res = (const float4*)(img + ((size_t)b * SS + row) * HID + col0 + tx * 8);
        float4 r0 = res[0], r1 = res[1];
        float4 o0, o1;
        o0.x = r0.x + gelu_exact(acc[i][0]);
        o0.y = r0.y + gelu_exact(acc[i][1]);
        o0.z = r0.z + gelu_exact(acc[i][2]);
        o0.w = r0.w + gelu_exact(acc[i][3]);
        o1.x = r1.x + gelu_exact(acc[i][4]);
        o1.y = r1.y + gelu_exact(acc[i][5]);
        o1.z = r1.z + gelu_exact(acc[i][6]);
        o1.w = r1.w + gelu_exact(acc[i][7]);
        float4* dst = (float4*)(out + ((size_t)b * SS + row) * HID + col0 + tx * 8);
        dst[0] = o0;
        dst[1] = o1;
    }
}

// =========================================================================
extern "C" void kernel_launch(void* const* d_in, const int* in_sizes, int n_in,
                              void* d_out, int out_size)
{
    const float* img = (const float*)d_in[0];   // [8,1024,768]
    const float* txt = (const float*)d_in[1];   // [8,2048,768]
    const float* Win = (const float*)d_in[2];   // [768,768]
    const float* Wup = (const float*)d_in[3];   // [64,256]
    float* out = (float*)d_out;                 // [8,1024,768]

    const int smemA = (2 * 64 * PADK + 2048) * (int)sizeof(float);   // 75776
    const int smemC = 256 * 68 * (int)sizeof(float);                 // 69632
    cudaFuncSetAttribute(attn_exp_kernel,  cudaFuncAttributeMaxDynamicSharedMemorySize, smemA);
    cudaFuncSetAttribute(upsample_kernel,  cudaFuncAttributeMaxDynamicSharedMemorySize, smemC);

    attn_exp_kernel<<<dim3(QCHUNKS, NHH, BB), 256, smemA>>>(img, txt);
    colsum_kernel<<<dim3(SS / 256, BH), 256>>>();
    pool_argmax_kernel<<<BH, 256>>>();
    upsample_kernel<<<BH, 256, smemC>>>(img, Wup);
    gemm_gelu_res_kernel<<<dim3(HID / 128, SS / 128, BB), 256>>>(Win, img, out);
}

// round 13
// speedup vs baseline: 2.1730x; 1.6511x over previous
#include <cuda_runtime.h>
#include <cuda_bf16.h>
#include <math.h>
#include <cstdint>

#define BB    8
#define NHH   12
#define HID   768
#define HD    64
#define SS    1024
#define QQ    2048
#define EDGE  32
#define KPOOL 16
#define PDIM  17
#define TQ    128
#define TS    128
#define QCHUNKS (QQ/TQ)     /* 16 */
#define BH    (BB*NHH)      /* 96 */

// ---------------- scratch (static device arrays; no allocation) ----------------
__device__ float          g_partial[(size_t)BH * QCHUNKS * SS];  // per-chunk column-sum partials
__device__ int            g_row[BH];
__device__ int            g_col[BH];
__device__ __nv_bfloat16  g_uph[(size_t)BB * SS * HID];          // upsample result, bf16 hi
__device__ __nv_bfloat16  g_upl[(size_t)BB * SS * HID];          // upsample result, bf16 lo
__device__ __nv_bfloat16  g_WinTh[(size_t)HID * HID];            // W_in transposed [n][k], hi
__device__ __nv_bfloat16  g_WinTl[(size_t)HID * HID];            // W_in transposed [n][k], lo

// ============================ helpers =================================
__device__ __forceinline__ uint32_t smem_u32(const void* p) {
    uint32_t a;
    asm("{ .reg .u64 t; cvta.to.shared.u64 t, %1; cvt.u32.u64 %0, t; }" : "=r"(a) : "l"(p));
    return a;
}
#define SWZ(o) ((o) ^ (((o) >> 3) & 0x70))

__device__ __forceinline__ void ldsm4(uint32_t* r, uint32_t addr) {
    asm volatile("ldmatrix.sync.aligned.m8n8.x4.shared.b16 {%0,%1,%2,%3}, [%4];"
                 : "=r"(r[0]), "=r"(r[1]), "=r"(r[2]), "=r"(r[3]) : "r"(addr));
}
__device__ __forceinline__ void mma16816(float* d, const uint32_t* a, const uint32_t* b) {
    asm volatile("mma.sync.aligned.m16n8k16.row.col.f32.bf16.bf16.f32 "
                 "{%0,%1,%2,%3}, {%4,%5,%6,%7}, {%8,%9}, {%0,%1,%2,%3};"
                 : "+f"(d[0]), "+f"(d[1]), "+f"(d[2]), "+f"(d[3])
                 : "r"(a[0]), "r"(a[1]), "r"(a[2]), "r"(a[3]), "r"(b[0]), "r"(b[1]));
}

// split one float4 into bf16 hi/lo pairs, store swizzled into 128B-row tiles
__device__ __forceinline__ void split_store(char* th, char* tl, int r, int seg, float4 v) {
    __nv_bfloat16 h0 = __float2bfloat16(v.x), h1 = __float2bfloat16(v.y);
    __nv_bfloat16 h2 = __float2bfloat16(v.z), h3 = __float2bfloat16(v.w);
    __nv_bfloat16 l0 = __float2bfloat16(v.x - __bfloat162float(h0));
    __nv_bfloat16 l1 = __float2bfloat16(v.y - __bfloat162float(h1));
    __nv_bfloat16 l2 = __float2bfloat16(v.z - __bfloat162float(h2));
    __nv_bfloat16 l3 = __float2bfloat16(v.w - __bfloat162float(h3));
    uint32_t sw = SWZ((uint32_t)(r * 128 + seg * 8));
    *(__nv_bfloat162*)(th + sw)     = __nv_bfloat162(h0, h1);
    *(__nv_bfloat162*)(th + sw + 4) = __nv_bfloat162(h2, h3);
    *(__nv_bfloat162*)(tl + sw)     = __nv_bfloat162(l0, l1);
    *(__nv_bfloat162*)(tl + sw + 4) = __nv_bfloat162(l2, l3);
}

// =========================================================================
// Kernel A: fused QK^T softmax column sums via mma.sync (bf16 3-term split).
// Pass A: rowsums -> smem linv.  Pass B: recompute, exp*linv, column sums.
// grid (16,12,8), 256 threads (8 warps = 4 row-blocks x 2 col-blocks).
// =========================================================================
__global__ __launch_bounds__(256, 2)
void qk_kernel(const float* __restrict__ img, const float* __restrict__ txt)
{
    extern __shared__ char smem[];
    char* Qh = smem;
    char* Ql = smem + 16384;
    char* Kh = smem + 32768;
    char* Kl = smem + 49152;
    float* scol   = (float*)(smem + 65536);          // 1024 floats
    float* rowred = (float*)(smem + 65536 + 4096);   // 128 floats
    const uint32_t sb = smem_u32(smem);
    const uint32_t qh_b = sb, ql_b = sb + 16384, kh_b = sb + 32768, kl_b = sb + 49152;

    const int chunk = blockIdx.x, h = blockIdx.y, b = blockIdx.z;
    const int tid = threadIdx.x, lane = tid & 31, wid = tid >> 5;
    const int warp_m = wid & 3, warp_n = wid >> 2;
    const int bh = b * NHH + h;
    const float SCALE = 0.18033688011112042f;   // log2(e)/8
    const int NST = SS / TS;

    if (tid < 128) rowred[tid] = 0.f;

    // ---- load + split Q tile (pre-scaled), rows 128 x 64 k ----
    {
        const float* qbase = txt + ((size_t)b * QQ + (size_t)chunk * TQ) * HID + h * HD;
        #pragma unroll
        for (int it = 0; it < 8; it++) {
            int i = tid + it * 256;
            int r = i >> 4, seg = i & 15;
            float4 v = __ldg((const float4*)(qbase + (size_t)r * HID) + seg);
            v.x *= SCALE; v.y *= SCALE; v.z *= SCALE; v.w *= SCALE;
            split_store(Qh, Ql, r, seg, v);
        }
    }
    const float* kroot = img + (size_t)b * SS * HID + h * HD;

    // per-lane ldmatrix offsets
    const int a_row  = warp_m * 32 + (lane & 15);                    // + mt*16
    const int a_koff = (lane >> 4) * 16;                             // + ks*32
    const int b_row  = warp_n * 64 + ((lane >> 4) * 8) + (lane & 7); // + np*16
    const int b_koff = ((lane >> 3) & 1) * 16;                       // + ks*32

    float rs[4] = {0.f, 0.f, 0.f, 0.f};
    float lv[4] = {0.f, 0.f, 0.f, 0.f};
    float* gpart = g_partial + ((size_t)bh * QCHUNKS + chunk) * SS;

    for (int pass = 0; pass < 2; pass++) {
        for (int st = 0; st < NST; st++) {
            __syncthreads();
            // ---- load + split K tile ----
            #pragma unroll
            for (int it = 0; it < 8; it++) {
                int i = tid + it * 256;
                int r = i >> 4, seg = i & 15;
                float4 v = __ldg((const float4*)(kroot + (size_t)(st * TS + r) * HID) + seg);
                split_store(Kh, Kl, r, seg, v);
            }
            __syncthreads();

            float c[2][8][4];
            #pragma unroll
            for (int mt = 0; mt < 2; mt++)
                #pragma unroll
                for (int nt = 0; nt < 8; nt++)
                    #pragma unroll
                    for (int j = 0; j < 4; j++) c[mt][nt][j] = 0.f;

            #pragma unroll
            for (int ks = 0; ks < 4; ks++) {
                uint32_t ah[2][4], al[2][4];
                #pragma unroll
                for (int mt = 0; mt < 2; mt++) {
                    uint32_t byte = (uint32_t)((a_row + mt * 16) * 128 + ks * 32 + a_koff);
                    ldsm4(ah[mt], qh_b + SWZ(byte));
                    ldsm4(al[mt], ql_b + SWZ(byte));
                }
                #pragma unroll
                for (int np = 0; np < 4; np++) {
                    uint32_t bhf[4], blf[4];
                    uint32_t byte = (uint32_t)((b_row + np * 16) * 128 + ks * 32 + b_koff);
                    ldsm4(bhf, kh_b + SWZ(byte));
                    ldsm4(blf, kl_b + SWZ(byte));
                    #pragma unroll
                    for (int mt = 0; mt < 2; mt++) {
                        mma16816(c[mt][np * 2],     ah[mt], bhf);
                        mma16816(c[mt][np * 2 + 1], ah[mt], bhf + 2);
                        mma16816(c[mt][np * 2],     al[mt], bhf);
                        mma16816(c[mt][np * 2 + 1], al[mt], bhf + 2);
                        mma16816(c[mt][np * 2],     ah[mt], blf);
                        mma16816(c[mt][np * 2 + 1], ah[mt], blf + 2);
                    }
                }
            }

            if (pass == 0) {
                #pragma unroll
                for (int mt = 0; mt < 2; mt++) {
                    float s0 = 0.f, s1 = 0.f;
                    #pragma unroll
                    for (int nt = 0; nt < 8; nt++) {
                        s0 += exp2f(c[mt][nt][0]) + exp2f(c[mt][nt][1]);
                        s1 += exp2f(c[mt][nt][2]) + exp2f(c[mt][nt][3]);
                    }
                    rs[mt * 2]     += s0;
                    rs[mt * 2 + 1] += s1;
                }
            } else {
                #pragma unroll
                for (int nt = 0; nt < 8; nt++) {
                    float v0 = 0.f, v1 = 0.f;
                    #pragma unroll
                    for (int mt = 0; mt < 2; mt++) {
                        v0 += exp2f(c[mt][nt][0]) * lv[mt * 2] + exp2f(c[mt][nt][2]) * lv[mt * 2 + 1];
                        v1 += exp2f(c[mt][nt][1]) * lv[mt * 2] + exp2f(c[mt][nt][3]) * lv[mt * 2 + 1];
                    }
                    v0 += __shfl_xor_sync(0xFFFFFFFFu, v0, 4);
                    v0 += __shfl_xor_sync(0xFFFFFFFFu, v0, 8);
                    v0 += __shfl_xor_sync(0xFFFFFFFFu, v0, 16);
                    v1 += __shfl_xor_sync(0xFFFFFFFFu, v1, 4);
                    v1 += __shfl_xor_sync(0xFFFFFFFFu, v1, 8);
                    v1 += __shfl_xor_sync(0xFFFFFFFFu, v1, 16);
                    if (lane < 4) {
                        int col = st * TS + warp_n * 64 + nt * 8 + lane * 2;
                        atomicAdd(&scol[col], v0);
                        atomicAdd(&scol[col + 1], v1);
                    }
                }
            }
        }

        if (pass == 0) {
            // reduce rs over the 4-lane column group
            #pragma unroll
            for (int k = 0; k < 4; k++) {
                rs[k] += __shfl_xor_sync(0xFFFFFFFFu, rs[k], 1);
                rs[k] += __shfl_xor_sync(0xFFFFFFFFu, rs[k], 2);
            }
            if ((lane & 3) == 0) {
                #pragma unroll
                for (int k = 0; k < 4; k++) {
                    int rl = warp_m * 32 + (k >> 1) * 16 + (k & 1) * 8 + (lane >> 2);
                    atomicAdd(&rowred[rl], rs[k]);
                }
            }
            __syncthreads();
            if (tid < 128) rowred[tid] = 1.0f / rowred[tid];
            for (int i = tid; i < SS; i += 256) scol[i] = 0.f;
            __syncthreads();
            #pragma unroll
            for (int k = 0; k < 4; k++)
                lv[k] = rowred[warp_m * 32 + (k >> 1) * 16 + (k & 1) * 8 + (lane >> 2)];
        }
    }

    __syncthreads();
    for (int i = tid; i < SS; i += 256) gpart[i] = scol[i];
}

// =========================================================================
// Kernel B: reduce partials, 16x16 pool (sums), argmax (first-index ties).
// =========================================================================
__global__ void pool_argmax_kernel()
{
    __shared__ float attn[SS];
    __shared__ float hsum[EDGE * PDIM];
    __shared__ float pooled[PDIM * PDIM];
    const int bh = blockIdx.x;
    const int tid = threadIdx.x;

    for (int s = tid; s < SS; s += 256) {
        float v = 0.f;
        #pragma unroll
        for (int c = 0; c < QCHUNKS; c++)
            v += g_partial[((size_t)bh * QCHUNKS + c) * SS + s];
        attn[s] = v;
    }
    __syncthreads();
    for (int t = tid; t < EDGE * PDIM; t += 256) {
        int r = t / PDIM, c = t % PDIM;
        float v = 0.f;
        #pragma unroll
        for (int j = 0; j < KPOOL; j++) v += attn[r * EDGE + c + j];
        hsum[t] = v;
    }
    __syncthreads();
    for (int t = tid; t < PDIM * PDIM; t += 256) {
        int r0 = t / PDIM, c = t % PDIM;
        float v = 0.f;
        #pragma unroll
        for (int r = 0; r < KPOOL; r++) v += hsum[(r0 + r) * PDIM + c];
        pooled[t] = v;
    }
    __syncthreads();
    if (tid == 0) {
        float best = -1e30f; int bi = 0;
        for (int t = 0; t < PDIM * PDIM; t++) {
            if (pooled[t] > best) { best = pooled[t]; bi = t; }
        }
        g_row[bh] = bi / PDIM;
        g_col[bh] = bi % PDIM;
    }
}

// =========================================================================
// Kernel C: gather argmax region, @ W_up, pixel-shuffle; write bf16 hi/lo.
// grid (96,4): blockIdx.y = 64-channel quadrant (dr = q>>1, dc = q&1).
// =========================================================================
__global__ __launch_bounds__(256)
void upsample_kernel(const float* __restrict__ img, const float* __restrict__ Wup)
{
    __shared__ float WsT[64 * 68];
    const int bh = blockIdx.x, q = blockIdx.y;
    const int b = bh / NHH, h = bh % NHH;
    const int tid = threadIdx.x;

    for (int i = tid; i < HD * 64; i += 256) {
        int k = i >> 6, cl = i & 63;
        WsT[cl * 68 + k] = Wup[k * 256 + q * 64 + cl];
    }
    const int row = g_row[bh], col = g_col[bh];
    __syncthreads();

    const int r2 = tid >> 4, c2 = tid & 15;
    const float* rp = img + ((size_t)b * SS + (size_t)(row + r2) * EDGE + (col + c2)) * HID + h * HD;
    float reg[HD];
    #pragma unroll
    for (int k4 = 0; k4 < 16; k4++) {
        float4 v = __ldg((const float4*)rp + k4);
        reg[k4 * 4 + 0] = v.x; reg[k4 * 4 + 1] = v.y;
        reg[k4 * 4 + 2] = v.z; reg[k4 * 4 + 3] = v.w;
    }
    const int dr = q >> 1, dc = q & 1;
    const int pos = (2 * r2 + dr) * EDGE + (2 * c2 + dc);
    const size_t ob = ((size_t)b * SS + pos) * HID + h * HD;
    for (int cl = 0; cl < 64; cl++) {
        float acc = 0.f;
        const float4* w = (const float4*)&WsT[cl * 68];
        #pragma unroll
        for (int k4 = 0; k4 < 16; k4++) {
            float4 wv = w[k4];
            acc += reg[k4 * 4 + 0] * wv.x + reg[k4 * 4 + 1] * wv.y
                 + reg[k4 * 4 + 2] * wv.z + reg[k4 * 4 + 3] * wv.w;
        }
        __nv_bfloat16 hi = __float2bfloat16(acc);
        g_uph[ob + cl] = hi;
        g_upl[ob + cl] = __float2bfloat16(acc - __bfloat162float(hi));
    }
}

// =========================================================================
// Kernel P: transpose + bf16-split W_in once:  WT[n][k] = W[k][n].
// =========================================================================
__global__ void winT_kernel(const float* __restrict__ W)
{
    __shared__ float t[32][33];
    const int n0 = blockIdx.x * 32, k0 = blockIdx.y * 32;
    const int tx = threadIdx.x, ty = threadIdx.y;
    for (int i = ty; i < 32; i += 8)
        t[i][tx] = W[(size_t)(k0 + i) * HID + n0 + tx];
    __syncthreads();
    for (int i = ty; i < 32; i += 8) {
        float x = t[tx][i];                 // = W[k0+tx][n0+i]
        __nv_bfloat16 hi = __float2bfloat16(x);
        size_t o = (size_t)(n0 + i) * HID + k0 + tx;
        g_WinTh[o] = hi;
        g_WinTl[o] = __float2bfloat16(x - __bfloat162float(hi));
    }
}

// =========================================================================
// Kernel D: out = residual + gelu_exact(up @ W_in), mma.sync 3-term split.
// grid (6,8,8), 256 threads, 128x128 tile, k-chunks of 64.
// =========================================================================
__device__ __forceinline__ float gelu_exact(float x)
{
    return 0.5f * x * (1.0f + erff(x * 0.70710678118654752440f));
}

__global__ __launch_bounds__(256, 2)
void gemm_gelu_res_kernel(const float* __restrict__ img, float* __restrict__ out)
{
    extern __shared__ char smem[];
    char* Ah = smem;
    char* Al = smem + 16384;
    char* Bh = smem + 32768;
    char* Bl = smem + 49152;
    const uint32_t sb = smem_u32(smem);
    const uint32_t ah_b = sb, al_b = sb + 16384, bh_b = sb + 32768, bl_b = sb + 49152;

    const int ct = blockIdx.x, rt = blockIdx.y, b = blockIdx.z;
    const int tid = threadIdx.x, lane = tid & 31, wid = tid >> 5;
    const int warp_m = wid & 3, warp_n = wid >> 2;
    const int row0 = rt * 128, col0 = ct * 128;

    const int a_row  = warp_m * 32 + (lane & 15);
    const int a_koff = (lane >> 4) * 16;
    const int b_row  = warp_n * 64 + ((lane >> 4) * 8) + (lane & 7);
    const int b_koff = ((lane >> 3) & 1) * 16;

    float c[2][8][4];
    #pragma unroll
    for (int mt = 0; mt < 2; mt++)
        #pragma unroll
        for (int nt = 0; nt < 8; nt++)
            #pragma unroll
            for (int j = 0; j < 4; j++) c[mt][nt][j] = 0.f;

    for (int kc = 0; kc < HID / 64; kc++) {
        __syncthreads();
        #pragma unroll
        for (int it = 0; it < 4; it++) {
            int i = tid + it * 256;
            int r = i >> 3, seg = i & 7;
            uint32_t sw = SWZ((uint32_t)(r * 128 + seg * 16));
            size_t ao = ((size_t)(b * SS + row0 + r)) * HID + kc * 64 + seg * 8;
            *(uint4*)(Ah + sw) = __ldg((const uint4*)(g_uph + ao));
            *(uint4*)(Al + sw) = __ldg((const uint4*)(g_upl + ao));
            size_t bo = ((size_t)(col0 + r)) * HID + kc * 64 + seg * 8;
            *(uint4*)(Bh + sw) = __ldg((const uint4*)(g_WinTh + bo));
            *(uint4*)(Bl + sw) = __ldg((const uint4*)(g_WinTl + bo));
        }
        __syncthreads();

        #pragma unroll
        for (int ks = 0; ks < 4; ks++) {
            uint32_t ah[2][4], al[2][4];
            #pragma unroll
            for (int mt = 0; mt < 2; mt++) {
                uint32_t byte = (uint32_t)((a_row + mt * 16) * 128 + ks * 32 + a_koff);
                ldsm4(ah[mt], ah_b + SWZ(byte));
                ldsm4(al[mt], al_b + SWZ(byte));
            }
            #pragma unroll
            for (int np = 0; np < 4; np++) {
                uint32_t bhf[4], blf[4];
                uint32_t byte = (uint32_t)((b_row + np * 16) * 128 + ks * 32 + b_koff);
                ldsm4(bhf, bh_b + SWZ(byte));
                ldsm4(blf, bl_b + SWZ(byte));
                #pragma unroll
                for (int mt = 0; mt < 2; mt++) {
                    mma16816(c[mt][np * 2],     ah[mt], bhf);
                    mma16816(c[mt][np * 2 + 1], ah[mt], bhf + 2);
                    mma16816(c[mt][np * 2],     al[mt], bhf);
                    mma16816(c[mt][np * 2 + 1], al[mt], bhf + 2);
                    mma16816(c[mt][np * 2],     ah[mt], blf);
                    mma16816(c[mt][np * 2 + 1], ah[mt], blf + 2);
                }
            }
        }
    }

    // epilogue: residual + gelu
    #pragma unroll
    for (int mt = 0; mt < 2; mt++) {
        int r0i = row0 + warp_m * 32 + mt * 16 + (lane >> 2);
        #pragma unroll
        for (int nt = 0; nt < 8; nt++) {
            int col = col0 + warp_n * 64 + nt * 8 + (lane & 3) * 2;
            {
                const float2 res = *(const float2*)(img + ((size_t)b * SS + r0i) * HID + col);
                float2 o;
                o.x = res.x + gelu_exact(c[mt][nt][0]);
                o.y = res.y + gelu_exact(c[mt][nt][1]);
                *(float2*)(out + ((size_t)b * SS + r0i) * HID + col) = o;
            }
            {
                const float2 res = *(const float2*)(img + ((size_t)b * SS + r0i + 8) * HID + col);
                float2 o;
                o.x = res.x + gelu_exact(c[mt][nt][2]);
                o.y = res.y + gelu_exact(c[mt][nt][3]);
                *(float2*)(out + ((size_t)b * SS + r0i + 8) * HID + col) = o;
            }
        }
    }
}

// =========================================================================
extern "C" void kernel_launch(void* const* d_in, const int* in_sizes, int n_in,
                              void* d_out, int out_size)
{
    const float* img = (const float*)d_in[0];   // [8,1024,768]
    const float* txt = (const float*)d_in[1];   // [8,2048,768]
    const float* Win = (const float*)d_in[2];   // [768,768]
    const float* Wup = (const float*)d_in[3];   // [64,256]
    float* out = (float*)d_out;                 // [8,1024,768]

    const int smemQK = 65536 + 4096 + 512;      // 70144
    const int smemGM = 65536;
    cudaFuncSetAttribute(qk_kernel,           cudaFuncAttributeMaxDynamicSharedMemorySize, smemQK);
    cudaFuncSetAttribute(gemm_gelu_res_kernel, cudaFuncAttributeMaxDynamicSharedMemorySize, smemGM);

    winT_kernel<<<dim3(HID / 32, HID / 32), dim3(32, 8)>>>(Win);
    qk_kernel<<<dim3(QCHUNKS, NHH, BB), 256, smemQK>>>(img, txt);
    pool_argmax_kernel<<<BH, 256>>>();
    upsample_kernel<<<dim3(BH, 4), 256>>>(img, Wup);
    gemm_gelu_res_kernel<<<dim3(HID / 128, SS / 128, BB), 256, smemGM>>>(img, out);
}

// round 14
// speedup vs baseline: 2.5394x; 1.1687x over previous
#include <cuda_runtime.h>
#include <cuda_bf16.h>
#include <math.h>
#include <cstdint>

#define BB    8
#define NHH   12
#define HID   768
#define HD    64
#define SS    1024
#define QQ    2048
#define EDGE  32
#define KPOOL 16
#define PDIM  17
#define TQ    128
#define TS    128
#define QCHUNKS (QQ/TQ)     /* 16 */
#define BH    (BB*NHH)      /* 96 */

// ---------------- scratch (static device arrays; no allocation) ----------------
__device__ float          g_partial[(size_t)BH * QCHUNKS * SS];  // per-chunk column-sum partials
__device__ int            g_row[BH];
__device__ int            g_col[BH];
__device__ __nv_bfloat16  g_uph[(size_t)BB * SS * HID];          // upsample result, bf16 hi
__device__ __nv_bfloat16  g_upl[(size_t)BB * SS * HID];          // upsample result, bf16 lo
__device__ __nv_bfloat16  g_WinTh[(size_t)HID * HID];            // W_in transposed [n][k], hi
__device__ __nv_bfloat16  g_WinTl[(size_t)HID * HID];            // W_in transposed [n][k], lo

// ============================ helpers =================================
__device__ __forceinline__ uint32_t smem_u32(const void* p) {
    uint32_t a;
    asm("{ .reg .u64 t; cvta.to.shared.u64 t, %1; cvt.u32.u64 %0, t; }" : "=r"(a) : "l"(p));
    return a;
}
#define SWZ(o) ((o) ^ (((o) >> 3) & 0x70))

__device__ __forceinline__ void ldsm4(uint32_t* r, uint32_t addr) {
    asm volatile("ldmatrix.sync.aligned.m8n8.x4.shared.b16 {%0,%1,%2,%3}, [%4];"
                 : "=r"(r[0]), "=r"(r[1]), "=r"(r[2]), "=r"(r[3]) : "r"(addr));
}
__device__ __forceinline__ void mma16816(float* d, const uint32_t* a, const uint32_t* b) {
    asm volatile("mma.sync.aligned.m16n8k16.row.col.f32.bf16.bf16.f32 "
                 "{%0,%1,%2,%3}, {%4,%5,%6,%7}, {%8,%9}, {%0,%1,%2,%3};"
                 : "+f"(d[0]), "+f"(d[1]), "+f"(d[2]), "+f"(d[3])
                 : "r"(a[0]), "r"(a[1]), "r"(a[2]), "r"(a[3]), "r"(b[0]), "r"(b[1]));
}

// split one float4 into bf16 hi/lo pairs, store swizzled into 128B-row tiles
__device__ __forceinline__ void split_store(char* th, char* tl, int r, int seg, float4 v) {
    __nv_bfloat16 h0 = __float2bfloat16(v.x), h1 = __float2bfloat16(v.y);
    __nv_bfloat16 h2 = __float2bfloat16(v.z), h3 = __float2bfloat16(v.w);
    __nv_bfloat16 l0 = __float2bfloat16(v.x - __bfloat162float(h0));
    __nv_bfloat16 l1 = __float2bfloat16(v.y - __bfloat162float(h1));
    __nv_bfloat16 l2 = __float2bfloat16(v.z - __bfloat162float(h2));
    __nv_bfloat16 l3 = __float2bfloat16(v.w - __bfloat162float(h3));
    uint32_t sw = SWZ((uint32_t)(r * 128 + seg * 8));
    *(__nv_bfloat162*)(th + sw)     = __nv_bfloat162(h0, h1);
    *(__nv_bfloat162*)(th + sw + 4) = __nv_bfloat162(h2, h3);
    *(__nv_bfloat162*)(tl + sw)     = __nv_bfloat162(l0, l1);
    *(__nv_bfloat162*)(tl + sw + 4) = __nv_bfloat162(l2, l3);
}
// hi-only variant (pass-1 K tiles)
__device__ __forceinline__ void hi_store(char* th, int r, int seg, float4 v) {
    __nv_bfloat16 h0 = __float2bfloat16(v.x), h1 = __float2bfloat16(v.y);
    __nv_bfloat16 h2 = __float2bfloat16(v.z), h3 = __float2bfloat16(v.w);
    uint32_t sw = SWZ((uint32_t)(r * 128 + seg * 8));
    *(__nv_bfloat162*)(th + sw)     = __nv_bfloat162(h0, h1);
    *(__nv_bfloat162*)(th + sw + 4) = __nv_bfloat162(h2, h3);
}

// =========================================================================
// Kernel A: fused QK^T softmax column sums via mma.sync.
// Pass 1 (single-term bf16): rowsums -> smem linv.   l_q error ~3e-5, only
//   rescales rows of the saliency map -> argmax unaffected.
// Pass 2 (3-term hi/lo split): recompute logits, exp*linv, column sums.
// grid (16,12,8), 256 threads (8 warps = 4 row-blocks x 2 col-blocks).
// =========================================================================
__global__ __launch_bounds__(256, 2)
void qk_kernel(const float* __restrict__ img, const float* __restrict__ txt)
{
    extern __shared__ char smem[];
    char* Qh = smem;
    char* Ql = smem + 16384;
    char* Kh = smem + 32768;
    char* Kl = smem + 49152;
    float* scol   = (float*)(smem + 65536);          // 1024 floats
    float* rowred = (float*)(smem + 65536 + 4096);   // 128 floats
    const uint32_t sb = smem_u32(smem);
    const uint32_t qh_b = sb, ql_b = sb + 16384, kh_b = sb + 32768, kl_b = sb + 49152;

    const int chunk = blockIdx.x, h = blockIdx.y, b = blockIdx.z;
    const int tid = threadIdx.x, lane = tid & 31, wid = tid >> 5;
    const int warp_m = wid & 3, warp_n = wid >> 2;
    const int bh = b * NHH + h;
    const float SCALE = 0.18033688011112042f;   // log2(e)/8
    const int NST = SS / TS;

    if (tid < 128) rowred[tid] = 0.f;

    // ---- load + split Q tile (pre-scaled), rows 128 x 64 k ----
    {
        const float* qbase = txt + ((size_t)b * QQ + (size_t)chunk * TQ) * HID + h * HD;
        #pragma unroll
        for (int it = 0; it < 8; it++) {
            int i = tid + it * 256;
            int r = i >> 4, seg = i & 15;
            float4 v = __ldg((const float4*)(qbase + (size_t)r * HID) + seg);
            v.x *= SCALE; v.y *= SCALE; v.z *= SCALE; v.w *= SCALE;
            split_store(Qh, Ql, r, seg, v);
        }
    }
    const float* kroot = img + (size_t)b * SS * HID + h * HD;

    // per-lane ldmatrix offsets
    const int a_row  = warp_m * 32 + (lane & 15);                    // + mt*16
    const int a_koff = (lane >> 4) * 16;                             // + ks*32
    const int b_row  = warp_n * 64 + ((lane >> 4) * 8) + (lane & 7); // + np*16
    const int b_koff = ((lane >> 3) & 1) * 16;                       // + ks*32

    float rs[4] = {0.f, 0.f, 0.f, 0.f};
    float lv[4];
    float* gpart = g_partial + ((size_t)bh * QCHUNKS + chunk) * SS;

    // ==================== PASS 1: single-term rowsums ====================
    for (int st = 0; st < NST; st++) {
        __syncthreads();
        #pragma unroll
        for (int it = 0; it < 8; it++) {
            int i = tid + it * 256;
            int r = i >> 4, seg = i & 15;
            float4 v = __ldg((const float4*)(kroot + (size_t)(st * TS + r) * HID) + seg);
            hi_store(Kh, r, seg, v);
        }
        __syncthreads();

        float c[2][8][4];
        #pragma unroll
        for (int mt = 0; mt < 2; mt++)
            #pragma unroll
            for (int nt = 0; nt < 8; nt++)
                #pragma unroll
                for (int j = 0; j < 4; j++) c[mt][nt][j] = 0.f;

        #pragma unroll
        for (int ks = 0; ks < 4; ks++) {
            uint32_t ah[2][4];
            #pragma unroll
            for (int mt = 0; mt < 2; mt++) {
                uint32_t byte = (uint32_t)((a_row + mt * 16) * 128 + ks * 32 + a_koff);
                ldsm4(ah[mt], qh_b + SWZ(byte));
            }
            #pragma unroll
            for (int np = 0; np < 4; np++) {
                uint32_t bhf[4];
                uint32_t byte = (uint32_t)((b_row + np * 16) * 128 + ks * 32 + b_koff);
                ldsm4(bhf, kh_b + SWZ(byte));
                #pragma unroll
                for (int mt = 0; mt < 2; mt++) {
                    mma16816(c[mt][np * 2],     ah[mt], bhf);
                    mma16816(c[mt][np * 2 + 1], ah[mt], bhf + 2);
                }
            }
        }

        #pragma unroll
        for (int mt = 0; mt < 2; mt++) {
            float s0 = 0.f, s1 = 0.f;
            #pragma unroll
            for (int nt = 0; nt < 8; nt++) {
                s0 += exp2f(c[mt][nt][0]) + exp2f(c[mt][nt][1]);
                s1 += exp2f(c[mt][nt][2]) + exp2f(c[mt][nt][3]);
            }
            rs[mt * 2]     += s0;
            rs[mt * 2 + 1] += s1;
        }
    }

    // reduce rs over the 4-lane column group, build linv
    #pragma unroll
    for (int k = 0; k < 4; k++) {
        rs[k] += __shfl_xor_sync(0xFFFFFFFFu, rs[k], 1);
        rs[k] += __shfl_xor_sync(0xFFFFFFFFu, rs[k], 2);
    }
    if ((lane & 3) == 0) {
        #pragma unroll
        for (int k = 0; k < 4; k++) {
            int rl = warp_m * 32 + (k >> 1) * 16 + (k & 1) * 8 + (lane >> 2);
            atomicAdd(&rowred[rl], rs[k]);
        }
    }
    __syncthreads();
    if (tid < 128) rowred[tid] = 1.0f / rowred[tid];
    for (int i = tid; i < SS; i += 256) scol[i] = 0.f;
    __syncthreads();
    #pragma unroll
    for (int k = 0; k < 4; k++)
        lv[k] = rowred[warp_m * 32 + (k >> 1) * 16 + (k & 1) * 8 + (lane >> 2)];

    // ==================== PASS 2: 3-term split column sums ====================
    for (int st = 0; st < NST; st++) {
        __syncthreads();
        #pragma unroll
        for (int it = 0; it < 8; it++) {
            int i = tid + it * 256;
            int r = i >> 4, seg = i & 15;
            float4 v = __ldg((const float4*)(kroot + (size_t)(st * TS + r) * HID) + seg);
            split_store(Kh, Kl, r, seg, v);
        }
        __syncthreads();

        float c[2][8][4];
        #pragma unroll
        for (int mt = 0; mt < 2; mt++)
            #pragma unroll
            for (int nt = 0; nt < 8; nt++)
                #pragma unroll
                for (int j = 0; j < 4; j++) c[mt][nt][j] = 0.f;

        #pragma unroll
        for (int ks = 0; ks < 4; ks++) {
            uint32_t ah[2][4], al[2][4];
            #pragma unroll
            for (int mt = 0; mt < 2; mt++) {
                uint32_t byte = (uint32_t)((a_row + mt * 16) * 128 + ks * 32 + a_koff);
                ldsm4(ah[mt], qh_b + SWZ(byte));
                ldsm4(al[mt], ql_b + SWZ(byte));
            }
            #pragma unroll
            for (int np = 0; np < 4; np++) {
                uint32_t bhf[4], blf[4];
                uint32_t byte = (uint32_t)((b_row + np * 16) * 128 + ks * 32 + b_koff);
                ldsm4(bhf, kh_b + SWZ(byte));
                ldsm4(blf, kl_b + SWZ(byte));
                #pragma unroll
                for (int mt = 0; mt < 2; mt++) {
                    mma16816(c[mt][np * 2],     ah[mt], bhf);
                    mma16816(c[mt][np * 2 + 1], ah[mt], bhf + 2);
                    mma16816(c[mt][np * 2],     al[mt], bhf);
                    mma16816(c[mt][np * 2 + 1], al[mt], bhf + 2);
                    mma16816(c[mt][np * 2],     ah[mt], blf);
                    mma16816(c[mt][np * 2 + 1], ah[mt], blf + 2);
                }
            }
        }

        #pragma unroll
        for (int nt = 0; nt < 8; nt++) {
            float v0 = 0.f, v1 = 0.f;
            #pragma unroll
            for (int mt = 0; mt < 2; mt++) {
                v0 += exp2f(c[mt][nt][0]) * lv[mt * 2] + exp2f(c[mt][nt][2]) * lv[mt * 2 + 1];
                v1 += exp2f(c[mt][nt][1]) * lv[mt * 2] + exp2f(c[mt][nt][3]) * lv[mt * 2 + 1];
            }
            v0 += __shfl_xor_sync(0xFFFFFFFFu, v0, 4);
            v0 += __shfl_xor_sync(0xFFFFFFFFu, v0, 8);
            v0 += __shfl_xor_sync(0xFFFFFFFFu, v0, 16);
            v1 += __shfl_xor_sync(0xFFFFFFFFu, v1, 4);
            v1 += __shfl_xor_sync(0xFFFFFFFFu, v1, 8);
            v1 += __shfl_xor_sync(0xFFFFFFFFu, v1, 16);
            if (lane < 4) {
                int col = st * TS + warp_n * 64 + nt * 8 + lane * 2;
                atomicAdd(&scol[col], v0);
                atomicAdd(&scol[col + 1], v1);
            }
        }
    }

    __syncthreads();
    for (int i = tid; i < SS; i += 256) gpart[i] = scol[i];
}

// =========================================================================
// Kernel B: reduce partials, 16x16 pool (sums), argmax (first-index ties).
// =========================================================================
__global__ void pool_argmax_kernel()
{
    __shared__ float attn[SS];
    __shared__ float hsum[EDGE * PDIM];
    __shared__ float pooled[PDIM * PDIM];
    const int bh = blockIdx.x;
    const int tid = threadIdx.x;

    for (int s = tid; s < SS; s += 256) {
        float v = 0.f;
        #pragma unroll
        for (int c = 0; c < QCHUNKS; c++)
            v += g_partial[((size_t)bh * QCHUNKS + c) * SS + s];
        attn[s] = v;
    }
    __syncthreads();
    for (int t = tid; t < EDGE * PDIM; t += 256) {
        int r = t / PDIM, c = t % PDIM;
        float v = 0.f;
        #pragma unroll
        for (int j = 0; j < KPOOL; j++) v += attn[r * EDGE + c + j];
        hsum[t] = v;
    }
    __syncthreads();
    for (int t = tid; t < PDIM * PDIM; t += 256) {
        int r0 = t / PDIM, c = t % PDIM;
        float v = 0.f;
        #pragma unroll
        for (int r = 0; r < KPOOL; r++) v += hsum[(r0 + r) * PDIM + c];
        pooled[t] = v;
    }
    __syncthreads();
    if (tid == 0) {
        float best = -1e30f; int bi = 0;
        for (int t = 0; t < PDIM * PDIM; t++) {
            if (pooled[t] > best) { best = pooled[t]; bi = t; }
        }
        g_row[bh] = bi / PDIM;
        g_col[bh] = bi % PDIM;
    }
}

// =========================================================================
// Kernel C: gather argmax region, @ W_up, pixel-shuffle; write bf16 hi/lo.
// grid (96,4). ILP: 4 partial accumulators per column + unroll-2 columns.
// =========================================================================
__global__ __launch_bounds__(256)
void upsample_kernel(const float* __restrict__ img, const float* __restrict__ Wup)
{
    __shared__ float WsT[64 * 68];
    const int bh = blockIdx.x, q = blockIdx.y;
    const int b = bh / NHH, h = bh % NHH;
    const int tid = threadIdx.x;

    for (int i = tid; i < HD * 64; i += 256) {
        int k = i >> 6, cl = i & 63;
        WsT[cl * 68 + k] = Wup[k * 256 + q * 64 + cl];
    }
    const int row = g_row[bh], col = g_col[bh];
    __syncthreads();

    const int r2 = tid >> 4, c2 = tid & 15;
    const float* rp = img + ((size_t)b * SS + (size_t)(row + r2) * EDGE + (col + c2)) * HID + h * HD;
    float reg[HD];
    #pragma unroll
    for (int k4 = 0; k4 < 16; k4++) {
        float4 v = __ldg((const float4*)rp + k4);
        reg[k4 * 4 + 0] = v.x; reg[k4 * 4 + 1] = v.y;
        reg[k4 * 4 + 2] = v.z; reg[k4 * 4 + 3] = v.w;
    }
    const int dr = q >> 1, dc = q & 1;
    const int pos = (2 * r2 + dr) * EDGE + (2 * c2 + dc);
    const size_t ob = ((size_t)b * SS + pos) * HID + h * HD;
    #pragma unroll 2
    for (int cl = 0; cl < 64; cl++) {
        const float4* w = (const float4*)&WsT[cl * 68];
        float a0 = 0.f, a1 = 0.f, a2 = 0.f, a3 = 0.f;
        #pragma unroll
        for (int k4 = 0; k4 < 16; k4 += 4) {
            float4 w0 = w[k4], w1 = w[k4 + 1], w2 = w[k4 + 2], w3 = w[k4 + 3];
            a0 += reg[k4 * 4 + 0]  * w0.x + reg[k4 * 4 + 1]  * w0.y
                + reg[k4 * 4 + 2]  * w0.z + reg[k4 * 4 + 3]  * w0.w;
            a1 += reg[k4 * 4 + 4]  * w1.x + reg[k4 * 4 + 5]  * w1.y
                + reg[k4 * 4 + 6]  * w1.z + reg[k4 * 4 + 7]  * w1.w;
            a2 += reg[k4 * 4 + 8]  * w2.x + reg[k4 * 4 + 9]  * w2.y
                + reg[k4 * 4 + 10] * w2.z + reg[k4 * 4 + 11] * w2.w;
            a3 += reg[k4 * 4 + 12] * w3.x + reg[k4 * 4 + 13] * w3.y
                + reg[k4 * 4 + 14] * w3.z + reg[k4 * 4 + 15] * w3.w;
        }
        float acc = (a0 + a1) + (a2 + a3);
        __nv_bfloat16 hi = __float2bfloat16(acc);
        g_uph[ob + cl] = hi;
        g_upl[ob + cl] = __float2bfloat16(acc - __bfloat162float(hi));
    }
}

// =========================================================================
// Kernel P: transpose + bf16-split W_in once:  WT[n][k] = W[k][n].
// =========================================================================
__global__ void winT_kernel(const float* __restrict__ W)
{
    __shared__ float t[32][33];
    const int n0 = blockIdx.x * 32, k0 = blockIdx.y * 32;
    const int tx = threadIdx.x, ty = threadIdx.y;
    for (int i = ty; i < 32; i += 8)
        t[i][tx] = W[(size_t)(k0 + i) * HID + n0 + tx];
    __syncthreads();
    for (int i = ty; i < 32; i += 8) {
        float x = t[tx][i];                 // = W[k0+tx][n0+i]
        __nv_bfloat16 hi = __float2bfloat16(x);
        size_t o = (size_t)(n0 + i) * HID + k0 + tx;
        g_WinTh[o] = hi;
        g_WinTl[o] = __float2bfloat16(x - __bfloat162float(hi));
    }
}

// =========================================================================
// Kernel D: out = residual + gelu_exact(up @ W_in), mma.sync 3-term split.
// grid (6,8,8), 256 threads, 128x128 tile, k-chunks of 64.
// =========================================================================
__device__ __forceinline__ float gelu_exact(float x)
{
    return 0.5f * x * (1.0f + erff(x * 0.70710678118654752440f));
}

__global__ __launch_bounds__(256, 2)
void gemm_gelu_res_kernel(const float* __restrict__ img, float* __restrict__ out)
{
    extern __shared__ char smem[];
    char* Ah = smem;
    char* Al = smem + 16384;
    char* Bh = smem + 32768;
    char* Bl = smem + 49152;
    const uint32_t sb = smem_u32(smem);
    const uint32_t ah_b = sb, al_b = sb + 16384, bh_b = sb + 32768, bl_b = sb + 49152;

    const int ct = blockIdx.x, rt = blockIdx.y, b = blockIdx.z;
    const int tid = threadIdx.x, lane = tid & 31, wid = tid >> 5;
    const int warp_m = wid & 3, warp_n = wid >> 2;
    const int row0 = rt * 128, col0 = ct * 128;

    const int a_row  = warp_m * 32 + (lane & 15);
    const int a_koff = (lane >> 4) * 16;
    const int b_row  = warp_n * 64 + ((lane >> 4) * 8) + (lane & 7);
    const int b_koff = ((lane >> 3) & 1) * 16;

    float c[2][8][4];
    #pragma unroll
    for (int mt = 0; mt < 2; mt++)
        #pragma unroll
        for (int nt = 0; nt < 8; nt++)
            #pragma unroll
            for (int j = 0; j < 4; j++) c[mt][nt][j] = 0.f;

    for (int kc = 0; kc < HID / 64; kc++) {
        __syncthreads();
        #pragma unroll
        for (int it = 0; it < 4; it++) {
            int i = tid + it * 256;
            int r = i >> 3, seg = i & 7;
            uint32_t sw = SWZ((uint32_t)(r * 128 + seg * 16));
            size_t ao = ((size_t)(b * SS + row0 + r)) * HID + kc * 64 + seg * 8;
            *(uint4*)(Ah + sw) = __ldg((const uint4*)(g_uph + ao));
            *(uint4*)(Al + sw) = __ldg((const uint4*)(g_upl + ao));
            size_t bo = ((size_t)(col0 + r)) * HID + kc * 64 + seg * 8;
            *(uint4*)(Bh + sw) = __ldg((const uint4*)(g_WinTh + bo));
            *(uint4*)(Bl + sw) = __ldg((const uint4*)(g_WinTl + bo));
        }
        __syncthreads();

        #pragma unroll
        for (int ks = 0; ks < 4; ks++) {
            uint32_t ah[2][4], al[2][4];
            #pragma unroll
            for (int mt = 0; mt < 2; mt++) {
                uint32_t byte = (uint32_t)((a_row + mt * 16) * 128 + ks * 32 + a_koff);
                ldsm4(ah[mt], ah_b + SWZ(byte));
                ldsm4(al[mt], al_b + SWZ(byte));
            }
            #pragma unroll
            for (int np = 0; np < 4; np++) {
                uint32_t bhf[4], blf[4];
                uint32_t byte = (uint32_t)((b_row + np * 16) * 128 + ks * 32 + b_koff);
                ldsm4(bhf, bh_b + SWZ(byte));
                ldsm4(blf, bl_b + SWZ(byte));
                #pragma unroll
                for (int mt = 0; mt < 2; mt++) {
                    mma16816(c[mt][np * 2],     ah[mt], bhf);
                    mma16816(c[mt][np * 2 + 1], ah[mt], bhf + 2);
                    mma16816(c[mt][np * 2],     al[mt], bhf);
                    mma16816(c[mt][np * 2 + 1], al[mt], bhf + 2);
                    mma16816(c[mt][np * 2],     ah[mt], blf);
                    mma16816(c[mt][np * 2 + 1], ah[mt], blf + 2);
                }
            }
        }
    }

    // epilogue: residual + gelu
    #pragma unroll
    for (int mt = 0; mt < 2; mt++) {
        int r0i = row0 + warp_m * 32 + mt * 16 + (lane >> 2);
        #pragma unroll
        for (int nt = 0; nt < 8; nt++) {
            int col = col0 + warp_n * 64 + nt * 8 + (lane & 3) * 2;
            {
                const float2 res = *(const float2*)(img + ((size_t)b * SS + r0i) * HID + col);
                float2 o;
                o.x = res.x + gelu_exact(c[mt][nt][0]);
                o.y = res.y + gelu_exact(c[mt][nt][1]);
                *(float2*)(out + ((size_t)b * SS + r0i) * HID + col) = o;
            }
            {
                const float2 res = *(const float2*)(img + ((size_t)b * SS + r0i + 8) * HID + col);
                float2 o;
                o.x = res.x + gelu_exact(c[mt][nt][2]);
                o.y = res.y + gelu_exact(c[mt][nt][3]);
                *(float2*)(out + ((size_t)b * SS + r0i + 8) * HID + col) = o;
            }
        }
    }
}

// =========================================================================
extern "C" void kernel_launch(void* const* d_in, const int* in_sizes, int n_in,
                              void* d_out, int out_size)
{
    const float* img = (const float*)d_in[0];   // [8,1024,768]
    const float* txt = (const float*)d_in[1];   // [8,2048,768]
    const float* Win = (const float*)d_in[2];   // [768,768]
    const float* Wup = (const float*)d_in[3];   // [64,256]
    float* out = (float*)d_out;                 // [8,1024,768]

    const int smemQK = 65536 + 4096 + 512;      // 70144
    const int smemGM = 65536;
    cudaFuncSetAttribute(qk_kernel,           cudaFuncAttributeMaxDynamicSharedMemorySize, smemQK);
    cudaFuncSetAttribute(gemm_gelu_res_kernel, cudaFuncAttributeMaxDynamicSharedMemorySize, smemGM);

    winT_kernel<<<dim3(HID / 32, HID / 32), dim3(32, 8)>>>(Win);
    qk_kernel<<<dim3(QCHUNKS, NHH, BB), 256, smemQK>>>(img, txt);
    pool_argmax_kernel<<<BH, 256>>>();
    upsample_kernel<<<dim3(BH, 4), 256>>>(img, Wup);
    gemm_gelu_res_kernel<<<dim3(HID / 128, SS / 128, BB), 256, smemGM>>>(img, out);
}

// round 15
// speedup vs baseline: 3.1714x; 1.2488x over previous
#include <cuda_runtime.h>
#include <cuda_bf16.h>
#include <math.h>
#include <cstdint>

#define BB    8
#define NHH   12
#define HID   768
#define HD    64
#define SS    1024
#define QQ    2048
#define EDGE  32
#define KPOOL 16
#define PDIM  17
#define TQ    128
#define TS    128
#define QCHUNKS (QQ/TQ)     /* 16 */
#define BH    (BB*NHH)      /* 96 */

// ---------------- scratch (static device arrays; no allocation) ----------------
__device__ float          g_partial[(size_t)BH * QCHUNKS * SS];  // per-chunk column-sum partials
__device__ int            g_row[BH];
__device__ int            g_col[BH];
__device__ __nv_bfloat16  g_uph[(size_t)BB * SS * HID];          // upsample result, bf16 hi
__device__ __nv_bfloat16  g_upl[(size_t)BB * SS * HID];          // upsample result, bf16 lo
__device__ __nv_bfloat16  g_WinTh[(size_t)HID * HID];            // W_in transposed [n][k], hi
__device__ __nv_bfloat16  g_WinTl[(size_t)HID * HID];            // W_in transposed [n][k], lo
__device__ __nv_bfloat16  g_WupTh[256 * HD];                     // W_up transposed [n][k], hi
__device__ __nv_bfloat16  g_WupTl[256 * HD];                     // W_up transposed [n][k], lo

// ============================ helpers =================================
__device__ __forceinline__ uint32_t smem_u32(const void* p) {
    uint32_t a;
    asm("{ .reg .u64 t; cvta.to.shared.u64 t, %1; cvt.u32.u64 %0, t; }" : "=r"(a) : "l"(p));
    return a;
}
#define SWZ(o) ((o) ^ (((o) >> 3) & 0x70))

__device__ __forceinline__ void ldsm4(uint32_t* r, uint32_t addr) {
    asm volatile("ldmatrix.sync.aligned.m8n8.x4.shared.b16 {%0,%1,%2,%3}, [%4];"
                 : "=r"(r[0]), "=r"(r[1]), "=r"(r[2]), "=r"(r[3]) : "r"(addr));
}
__device__ __forceinline__ void mma16816(float* d, const uint32_t* a, const uint32_t* b) {
    asm volatile("mma.sync.aligned.m16n8k16.row.col.f32.bf16.bf16.f32 "
                 "{%0,%1,%2,%3}, {%4,%5,%6,%7}, {%8,%9}, {%0,%1,%2,%3};"
                 : "+f"(d[0]), "+f"(d[1]), "+f"(d[2]), "+f"(d[3])
                 : "r"(a[0]), "r"(a[1]), "r"(a[2]), "r"(a[3]), "r"(b[0]), "r"(b[1]));
}

// split one float4 into bf16 hi/lo pairs, store swizzled into 128B-row tiles
__device__ __forceinline__ void split_store(char* th, char* tl, int r, int seg, float4 v) {
    __nv_bfloat16 h0 = __float2bfloat16(v.x), h1 = __float2bfloat16(v.y);
    __nv_bfloat16 h2 = __float2bfloat16(v.z), h3 = __float2bfloat16(v.w);
    __nv_bfloat16 l0 = __float2bfloat16(v.x - __bfloat162float(h0));
    __nv_bfloat16 l1 = __float2bfloat16(v.y - __bfloat162float(h1));
    __nv_bfloat16 l2 = __float2bfloat16(v.z - __bfloat162float(h2));
    __nv_bfloat16 l3 = __float2bfloat16(v.w - __bfloat162float(h3));
    uint32_t sw = SWZ((uint32_t)(r * 128 + seg * 8));
    *(__nv_bfloat162*)(th + sw)     = __nv_bfloat162(h0, h1);
    *(__nv_bfloat162*)(th + sw + 4) = __nv_bfloat162(h2, h3);
    *(__nv_bfloat162*)(tl + sw)     = __nv_bfloat162(l0, l1);
    *(__nv_bfloat162*)(tl + sw + 4) = __nv_bfloat162(l2, l3);
}
// hi-only variant (pass-1 K tiles)
__device__ __forceinline__ void hi_store(char* th, int r, int seg, float4 v) {
    __nv_bfloat16 h0 = __float2bfloat16(v.x), h1 = __float2bfloat16(v.y);
    __nv_bfloat16 h2 = __float2bfloat16(v.z), h3 = __float2bfloat16(v.w);
    uint32_t sw = SWZ((uint32_t)(r * 128 + seg * 8));
    *(__nv_bfloat162*)(th + sw)     = __nv_bfloat162(h0, h1);
    *(__nv_bfloat162*)(th + sw + 4) = __nv_bfloat162(h2, h3);
}

// =========================================================================
// Kernel A: fused QK^T softmax column sums via mma.sync.
// Pass 1 (single-term bf16): rowsums -> smem linv (l_q err ~3e-5; argmax safe).
// Pass 2 (3-term hi/lo split): recompute logits, exp*linv, column sums.
// grid (16,12,8), 256 threads (8 warps = 4 row-blocks x 2 col-blocks).
// =========================================================================
__global__ __launch_bounds__(256, 2)
void qk_kernel(const float* __restrict__ img, const float* __restrict__ txt)
{
    extern __shared__ char smem[];
    char* Qh = smem;
    char* Ql = smem + 16384;
    char* Kh = smem + 32768;
    char* Kl = smem + 49152;
    float* scol   = (float*)(smem + 65536);          // 1024 floats
    float* rowred = (float*)(smem + 65536 + 4096);   // 128 floats
    const uint32_t sb = smem_u32(smem);
    const uint32_t qh_b = sb, ql_b = sb + 16384, kh_b = sb + 32768, kl_b = sb + 49152;

    const int chunk = blockIdx.x, h = blockIdx.y, b = blockIdx.z;
    const int tid = threadIdx.x, lane = tid & 31, wid = tid >> 5;
    const int warp_m = wid & 3, warp_n = wid >> 2;
    const int bh = b * NHH + h;
    const float SCALE = 0.18033688011112042f;   // log2(e)/8
    const int NST = SS / TS;

    if (tid < 128) rowred[tid] = 0.f;

    // ---- load + split Q tile (pre-scaled), rows 128 x 64 k ----
    {
        const float* qbase = txt + ((size_t)b * QQ + (size_t)chunk * TQ) * HID + h * HD;
        #pragma unroll
        for (int it = 0; it < 8; it++) {
            int i = tid + it * 256;
            int r = i >> 4, seg = i & 15;
            float4 v = __ldg((const float4*)(qbase + (size_t)r * HID) + seg);
            v.x *= SCALE; v.y *= SCALE; v.z *= SCALE; v.w *= SCALE;
            split_store(Qh, Ql, r, seg, v);
        }
    }
    const float* kroot = img + (size_t)b * SS * HID + h * HD;

    // per-lane ldmatrix offsets
    const int a_row  = warp_m * 32 + (lane & 15);                    // + mt*16
    const int a_koff = (lane >> 4) * 16;                             // + ks*32
    const int b_row  = warp_n * 64 + ((lane >> 4) * 8) + (lane & 7); // + np*16
    const int b_koff = ((lane >> 3) & 1) * 16;                       // + ks*32

    float rs[4] = {0.f, 0.f, 0.f, 0.f};
    float lv[4];
    float* gpart = g_partial + ((size_t)bh * QCHUNKS + chunk) * SS;

    // ==================== PASS 1: single-term rowsums ====================
    for (int st = 0; st < NST; st++) {
        __syncthreads();
        #pragma unroll
        for (int it = 0; it < 8; it++) {
            int i = tid + it * 256;
            int r = i >> 4, seg = i & 15;
            float4 v = __ldg((const float4*)(kroot + (size_t)(st * TS + r) * HID) + seg);
            hi_store(Kh, r, seg, v);
        }
        __syncthreads();

        float c[2][8][4];
        #pragma unroll
        for (int mt = 0; mt < 2; mt++)
            #pragma unroll
            for (int nt = 0; nt < 8; nt++)
                #pragma unroll
                for (int j = 0; j < 4; j++) c[mt][nt][j] = 0.f;

        #pragma unroll
        for (int ks = 0; ks < 4; ks++) {
            uint32_t ah[2][4];
            #pragma unroll
            for (int mt = 0; mt < 2; mt++) {
                uint32_t byte = (uint32_t)((a_row + mt * 16) * 128 + ks * 32 + a_koff);
                ldsm4(ah[mt], qh_b + SWZ(byte));
            }
            #pragma unroll
            for (int np = 0; np < 4; np++) {
                uint32_t bhf[4];
                uint32_t byte = (uint32_t)((b_row + np * 16) * 128 + ks * 32 + b_koff);
                ldsm4(bhf, kh_b + SWZ(byte));
                #pragma unroll
                for (int mt = 0; mt < 2; mt++) {
                    mma16816(c[mt][np * 2],     ah[mt], bhf);
                    mma16816(c[mt][np * 2 + 1], ah[mt], bhf + 2);
                }
            }
        }

        #pragma unroll
        for (int mt = 0; mt < 2; mt++) {
            float s0 = 0.f, s1 = 0.f;
            #pragma unroll
            for (int nt = 0; nt < 8; nt++) {
                s0 += exp2f(c[mt][nt][0]) + exp2f(c[mt][nt][1]);
                s1 += exp2f(c[mt][nt][2]) + exp2f(c[mt][nt][3]);
            }
            rs[mt * 2]     += s0;
            rs[mt * 2 + 1] += s1;
        }
    }

    // reduce rs over the 4-lane column group, build linv
    #pragma unroll
    for (int k = 0; k < 4; k++) {
        rs[k] += __shfl_xor_sync(0xFFFFFFFFu, rs[k], 1);
        rs[k] += __shfl_xor_sync(0xFFFFFFFFu, rs[k], 2);
    }
    if ((lane & 3) == 0) {
        #pragma unroll
        for (int k = 0; k < 4; k++) {
            int rl = warp_m * 32 + (k >> 1) * 16 + (k & 1) * 8 + (lane >> 2);
            atomicAdd(&rowred[rl], rs[k]);
        }
    }
    __syncthreads();
    if (tid < 128) rowred[tid] = 1.0f / rowred[tid];
    for (int i = tid; i < SS; i += 256) scol[i] = 0.f;
    __syncthreads();
    #pragma unroll
    for (int k = 0; k < 4; k++)
        lv[k] = rowred[warp_m * 32 + (k >> 1) * 16 + (k & 1) * 8 + (lane >> 2)];

    // ==================== PASS 2: 3-term split column sums ====================
    for (int st = 0; st < NST; st++) {
        __syncthreads();
        #pragma unroll
        for (int it = 0; it < 8; it++) {
            int i = tid + it * 256;
            int r = i >> 4, seg = i & 15;
            float4 v = __ldg((const float4*)(kroot + (size_t)(st * TS + r) * HID) + seg);
            split_store(Kh, Kl, r, seg, v);
        }
        __syncthreads();

        float c[2][8][4];
        #pragma unroll
        for (int mt = 0; mt < 2; mt++)
            #pragma unroll
            for (int nt = 0; nt < 8; nt++)
                #pragma unroll
                for (int j = 0; j < 4; j++) c[mt][nt][j] = 0.f;

        #pragma unroll
        for (int ks = 0; ks < 4; ks++) {
            uint32_t ah[2][4], al[2][4];
            #pragma unroll
            for (int mt = 0; mt < 2; mt++) {
                uint32_t byte = (uint32_t)((a_row + mt * 16) * 128 + ks * 32 + a_koff);
                ldsm4(ah[mt], qh_b + SWZ(byte));
                ldsm4(al[mt], ql_b + SWZ(byte));
            }
            #pragma unroll
            for (int np = 0; np < 4; np++) {
                uint32_t bhf[4], blf[4];
                uint32_t byte = (uint32_t)((b_row + np * 16) * 128 + ks * 32 + b_koff);
                ldsm4(bhf, kh_b + SWZ(byte));
                ldsm4(blf, kl_b + SWZ(byte));
                #pragma unroll
                for (int mt = 0; mt < 2; mt++) {
                    mma16816(c[mt][np * 2],     ah[mt], bhf);
                    mma16816(c[mt][np * 2 + 1], ah[mt], bhf + 2);
                    mma16816(c[mt][np * 2],     al[mt], bhf);
                    mma16816(c[mt][np * 2 + 1], al[mt], bhf + 2);
                    mma16816(c[mt][np * 2],     ah[mt], blf);
                    mma16816(c[mt][np * 2 + 1], ah[mt], blf + 2);
                }
            }
        }

        #pragma unroll
        for (int nt = 0; nt < 8; nt++) {
            float v0 = 0.f, v1 = 0.f;
            #pragma unroll
            for (int mt = 0; mt < 2; mt++) {
                v0 += exp2f(c[mt][nt][0]) * lv[mt * 2] + exp2f(c[mt][nt][2]) * lv[mt * 2 + 1];
                v1 += exp2f(c[mt][nt][1]) * lv[mt * 2] + exp2f(c[mt][nt][3]) * lv[mt * 2 + 1];
            }
            v0 += __shfl_xor_sync(0xFFFFFFFFu, v0, 4);
            v0 += __shfl_xor_sync(0xFFFFFFFFu, v0, 8);
            v0 += __shfl_xor_sync(0xFFFFFFFFu, v0, 16);
            v1 += __shfl_xor_sync(0xFFFFFFFFu, v1, 4);
            v1 += __shfl_xor_sync(0xFFFFFFFFu, v1, 8);
            v1 += __shfl_xor_sync(0xFFFFFFFFu, v1, 16);
            if (lane < 4) {
                int col = st * TS + warp_n * 64 + nt * 8 + lane * 2;
                atomicAdd(&scol[col], v0);
                atomicAdd(&scol[col + 1], v1);
            }
        }
    }

    __syncthreads();
    for (int i = tid; i < SS; i += 256) gpart[i] = scol[i];
}

// =========================================================================
// Kernel B: reduce partials, 16x16 pool (sums), argmax (first-index ties).
// =========================================================================
__global__ void pool_argmax_kernel()
{
    __shared__ float attn[SS];
    __shared__ float hsum[EDGE * PDIM];
    __shared__ float pooled[PDIM * PDIM];
    const int bh = blockIdx.x;
    const int tid = threadIdx.x;

    for (int s = tid; s < SS; s += 256) {
        float v = 0.f;
        #pragma unroll
        for (int c = 0; c < QCHUNKS; c++)
            v += g_partial[((size_t)bh * QCHUNKS + c) * SS + s];
        attn[s] = v;
    }
    __syncthreads();
    for (int t = tid; t < EDGE * PDIM; t += 256) {
        int r = t / PDIM, c = t % PDIM;
        float v = 0.f;
        #pragma unroll
        for (int j = 0; j < KPOOL; j++) v += attn[r * EDGE + c + j];
        hsum[t] = v;
    }
    __syncthreads();
    for (int t = tid; t < PDIM * PDIM; t += 256) {
        int r0 = t / PDIM, c = t % PDIM;
        float v = 0.f;
        #pragma unroll
        for (int r = 0; r < KPOOL; r++) v += hsum[(r0 + r) * PDIM + c];
        pooled[t] = v;
    }
    __syncthreads();
    if (tid == 0) {
        float best = -1e30f; int bi = 0;
        for (int t = 0; t < PDIM * PDIM; t++) {
            if (pooled[t] > best) { best = pooled[t]; bi = t; }
        }
        g_row[bh] = bi / PDIM;
        g_col[bh] = bi % PDIM;
    }
}

// =========================================================================
// Kernel P2: transpose + bf16-split W_up once: WupT[n][k] = Wup[k][n].
// =========================================================================
__global__ void wupT_kernel(const float* __restrict__ Wup)
{
    int idx = blockIdx.x * 256 + threadIdx.x;   // 64 x 256 = 16384
    int k = idx >> 8, n = idx & 255;
    float x = Wup[idx];
    __nv_bfloat16 hi = __float2bfloat16(x);
    g_WupTh[n * HD + k] = hi;
    g_WupTl[n * HD + k] = __float2bfloat16(x - __bfloat162float(hi));
}

// =========================================================================
// Kernel C: upsample as mma GEMM: region[256x64] @ WupT^T -> pixel-shuffled
// bf16 hi/lo. grid (96,4): bq = (rt<<1)|ct, 128x128x64 tile per block.
// =========================================================================
__global__ __launch_bounds__(256)
void upsample_mma_kernel(const float* __restrict__ img)
{
    extern __shared__ char smem[];
    char* Ah = smem;
    char* Al = smem + 16384;
    char* Bh = smem + 32768;
    char* Bl = smem + 49152;
    const uint32_t sb = smem_u32(smem);
    const uint32_t ah_b = sb, al_b = sb + 16384, bh_b = sb + 32768, bl_b = sb + 49152;

    const int bh = blockIdx.x, bq = blockIdx.y;
    const int rt = bq >> 1, ct = bq & 1;
    const int b = bh / NHH, h = bh % NHH;
    const int tid = threadIdx.x, lane = tid & 31, wid = tid >> 5;
    const int warp_m = wid & 3, warp_n = wid >> 2;
    const int row = g_row[bh], col = g_col[bh];

    // ---- A: 128 region tokens (coalesced 256B rows), split bf16 hi/lo ----
    #pragma unroll
    for (int it = 0; it < 8; it++) {
        int i = tid + it * 256;
        int r = i >> 4, seg = i & 15;
        int t = rt * 128 + r;
        int r2 = t >> 4, c2 = t & 15;
        const float* rp = img + ((size_t)b * SS + (size_t)(row + r2) * EDGE + (col + c2)) * HID + h * HD;
        float4 v = __ldg((const float4*)rp + seg);
        split_store(Ah, Al, r, seg, v);
    }
    // ---- B: 128 rows of WupT (pre-split bf16) ----
    #pragma unroll
    for (int it = 0; it < 4; it++) {
        int i = tid + it * 256;
        int r = i >> 3, seg = i & 7;
        uint32_t sw = SWZ((uint32_t)(r * 128 + seg * 16));
        size_t o = (size_t)(ct * 128 + r) * HD + seg * 8;
        *(uint4*)(Bh + sw) = *(const uint4*)(g_WupTh + o);
        *(uint4*)(Bl + sw) = *(const uint4*)(g_WupTl + o);
    }
    __syncthreads();

    const int a_row  = warp_m * 32 + (lane & 15);
    const int a_koff = (lane >> 4) * 16;
    const int b_row  = warp_n * 64 + ((lane >> 4) * 8) + (lane & 7);
    const int b_koff = ((lane >> 3) & 1) * 16;

    float c[2][8][4];
    #pragma unroll
    for (int mt = 0; mt < 2; mt++)
        #pragma unroll
        for (int nt = 0; nt < 8; nt++)
            #pragma unroll
            for (int j = 0; j < 4; j++) c[mt][nt][j] = 0.f;

    #pragma unroll
    for (int ks = 0; ks < 4; ks++) {
        uint32_t ah[2][4], al[2][4];
        #pragma unroll
        for (int mt = 0; mt < 2; mt++) {
            uint32_t byte = (uint32_t)((a_row + mt * 16) * 128 + ks * 32 + a_koff);
            ldsm4(ah[mt], ah_b + SWZ(byte));
            ldsm4(al[mt], al_b + SWZ(byte));
        }
        #pragma unroll
        for (int np = 0; np < 4; np++) {
            uint32_t bhf[4], blf[4];
            uint32_t byte = (uint32_t)((b_row + np * 16) * 128 + ks * 32 + b_koff);
            ldsm4(bhf, bh_b + SWZ(byte));
            ldsm4(blf, bl_b + SWZ(byte));
            #pragma unroll
            for (int mt = 0; mt < 2; mt++) {
                mma16816(c[mt][np * 2],     ah[mt], bhf);
                mma16816(c[mt][np * 2 + 1], ah[mt], bhf + 2);
                mma16816(c[mt][np * 2],     al[mt], bhf);
                mma16816(c[mt][np * 2 + 1], al[mt], bhf + 2);
                mma16816(c[mt][np * 2],     ah[mt], blf);
                mma16816(c[mt][np * 2 + 1], ah[mt], blf + 2);
            }
        }
    }

    // ---- epilogue: pixel-shuffle scatter, bf16 hi/lo pairs ----
    #pragma unroll
    for (int mt = 0; mt < 2; mt++) {
        #pragma unroll
        for (int nt = 0; nt < 8; nt++) {
            int col_local = warp_n * 64 + nt * 8 + (lane & 3) * 2;
            int co = ct * 128 + col_local;
            int dr = co >> 7, dc = (co >> 6) & 1, d = co & 63;
            #pragma unroll
            for (int half = 0; half < 2; half++) {
                int rl = warp_m * 32 + mt * 16 + (lane >> 2) + half * 8;
                int t = rt * 128 + rl;
                int r2 = t >> 4, c2 = t & 15;
                int pos = (2 * r2 + dr) * EDGE + (2 * c2 + dc);
                size_t o = ((size_t)b * SS + pos) * HID + h * HD + d;
                float x0 = c[mt][nt][half * 2], x1 = c[mt][nt][half * 2 + 1];
                __nv_bfloat16 h0 = __float2bfloat16(x0);
                __nv_bfloat16 h1 = __float2bfloat16(x1);
                __nv_bfloat16 l0 = __float2bfloat16(x0 - __bfloat162float(h0));
                __nv_bfloat16 l1 = __float2bfloat16(x1 - __bfloat162float(h1));
                *(__nv_bfloat162*)(g_uph + o) = __nv_bfloat162(h0, h1);
                *(__nv_bfloat162*)(g_upl + o) = __nv_bfloat162(l0, l1);
            }
        }
    }
}

// =========================================================================
// Kernel P: transpose + bf16-split W_in once:  WT[n][k] = W[k][n].
// =========================================================================
__global__ void winT_kernel(const float* __restrict__ W)
{
    __shared__ float t[32][33];
    const int n0 = blockIdx.x * 32, k0 = blockIdx.y * 32;
    const int tx = threadIdx.x, ty = threadIdx.y;
    for (int i = ty; i < 32; i += 8)
        t[i][tx] = W[(size_t)(k0 + i) * HID + n0 + tx];
    __syncthreads();
    for (int i = ty; i < 32; i += 8) {
        float x = t[tx][i];                 // = W[k0+tx][n0+i]
        __nv_bfloat16 hi = __float2bfloat16(x);
        size_t o = (size_t)(n0 + i) * HID + k0 + tx;
        g_WinTh[o] = hi;
        g_WinTl[o] = __float2bfloat16(x - __bfloat162float(hi));
    }
}

// =========================================================================
// Kernel D: out = residual + gelu_exact(up @ W_in), mma.sync 3-term split.
// grid (6,8,8), 256 threads, 128x128 tile, k-chunks of 64.
// =========================================================================
__device__ __forceinline__ float gelu_exact(float x)
{
    return 0.5f * x * (1.0f + erff(x * 0.70710678118654752440f));
}

__global__ __launch_bounds__(256, 2)
void gemm_gelu_res_kernel(const float* __restrict__ img, float* __restrict__ out)
{
    extern __shared__ char smem[];
    char* Ah = smem;
    char* Al = smem + 16384;
    char* Bh = smem + 32768;
    char* Bl = smem + 49152;
    const uint32_t sb = smem_u32(smem);
    const uint32_t ah_b = sb, al_b = sb + 16384, bh_b = sb + 32768, bl_b = sb + 49152;

    const int ct = blockIdx.x, rt = blockIdx.y, b = blockIdx.z;
    const int tid = threadIdx.x, lane = tid & 31, wid = tid >> 5;
    const int warp_m = wid & 3, warp_n = wid >> 2;
    const int row0 = rt * 128, col0 = ct * 128;

    const int a_row  = warp_m * 32 + (lane & 15);
    const int a_koff = (lane >> 4) * 16;
    const int b_row  = warp_n * 64 + ((lane >> 4) * 8) + (lane & 7);
    const int b_koff = ((lane >> 3) & 1) * 16;

    float c[2][8][4];
    #pragma unroll
    for (int mt = 0; mt < 2; mt++)
        #pragma unroll
        for (int nt = 0; nt < 8; nt++)
            #pragma unroll
            for (int j = 0; j < 4; j++) c[mt][nt][j] = 0.f;

    for (int kc = 0; kc < HID / 64; kc++) {
        __syncthreads();
        #pragma unroll
        for (int it = 0; it < 4; it++) {
            int i = tid + it * 256;
            int r = i >> 3, seg = i & 7;
            uint32_t sw = SWZ((uint32_t)(r * 128 + seg * 16));
            size_t ao = ((size_t)(b * SS + row0 + r)) * HID + kc * 64 + seg * 8;
            *(uint4*)(Ah + sw) = __ldg((const uint4*)(g_uph + ao));
            *(uint4*)(Al + sw) = __ldg((const uint4*)(g_upl + ao));
            size_t bo = ((size_t)(col0 + r)) * HID + kc * 64 + seg * 8;
            *(uint4*)(Bh + sw) = __ldg((const uint4*)(g_WinTh + bo));
            *(uint4*)(Bl + sw) = __ldg((const uint4*)(g_WinTl + bo));
        }
        __syncthreads();

        #pragma unroll
        for (int ks = 0; ks < 4; ks++) {
            uint32_t ah[2][4], al[2][4];
            #pragma unroll
            for (int mt = 0; mt < 2; mt++) {
                uint32_t byte = (uint32_t)((a_row + mt * 16) * 128 + ks * 32 + a_koff);
                ldsm4(ah[mt], ah_b + SWZ(byte));
                ldsm4(al[mt], al_b + SWZ(byte));
            }
            #pragma unroll
            for (int np = 0; np < 4; np++) {
                uint32_t bhf[4], blf[4];
                uint32_t byte = (uint32_t)((b_row + np * 16) * 128 + ks * 32 + b_koff);
                ldsm4(bhf, bh_b + SWZ(byte));
                ldsm4(blf, bl_b + SWZ(byte));
                #pragma unroll
                for (int mt = 0; mt < 2; mt++) {
                    mma16816(c[mt][np * 2],     ah[mt], bhf);
                    mma16816(c[mt][np * 2 + 1], ah[mt], bhf + 2);
                    mma16816(c[mt][np * 2],     al[mt], bhf);
                    mma16816(c[mt][np * 2 + 1], al[mt], bhf + 2);
                    mma16816(c[mt][np * 2],     ah[mt], blf);
                    mma16816(c[mt][np * 2 + 1], ah[mt], blf + 2);
                }
            }
        }
    }

    // epilogue: residual + gelu
    #pragma unroll
    for (int mt = 0; mt < 2; mt++) {
        int r0i = row0 + warp_m * 32 + mt * 16 + (lane >> 2);
        #pragma unroll
        for (int nt = 0; nt < 8; nt++) {
            int col = col0 + warp_n * 64 + nt * 8 + (lane & 3) * 2;
            {
                const float2 res = *(const float2*)(img + ((size_t)b * SS + r0i) * HID + col);
                float2 o;
                o.x = res.x + gelu_exact(c[mt][nt][0]);
                o.y = res.y + gelu_exact(c[mt][nt][1]);
                *(float2*)(out + ((size_t)b * SS + r0i) * HID + col) = o;
            }
            {
                const float2 res = *(const float2*)(img + ((size_t)b * SS + r0i + 8) * HID + col);
                float2 o;
                o.x = res.x + gelu_exact(c[mt][nt][2]);
                o.y = res.y + gelu_exact(c[mt][nt][3]);
                *(float2*)(out + ((size_t)b * SS + r0i + 8) * HID + col) = o;
            }
        }
    }
}

// =========================================================================
extern "C" void kernel_launch(void* const* d_in, const int* in_sizes, int n_in,
                              void* d_out, int out_size)
{
    const float* img = (const float*)d_in[0];   // [8,1024,768]
    const float* txt = (const float*)d_in[1];   // [8,2048,768]
    const float* Win = (const float*)d_in[2];   // [768,768]
    const float* Wup = (const float*)d_in[3];   // [64,256]
    float* out = (float*)d_out;                 // [8,1024,768]

    const int smemQK = 65536 + 4096 + 512;      // 70144
    const int smemGM = 65536;
    cudaFuncSetAttribute(qk_kernel,            cudaFuncAttributeMaxDynamicSharedMemorySize, smemQK);
    cudaFuncSetAttribute(gemm_gelu_res_kernel, cudaFuncAttributeMaxDynamicSharedMemorySize, smemGM);
    cudaFuncSetAttribute(upsample_mma_kernel,  cudaFuncAttributeMaxDynamicSharedMemorySize, smemGM);

    winT_kernel<<<dim3(HID / 32, HID / 32), dim3(32, 8)>>>(Win);
    wupT_kernel<<<64, 256>>>(Wup);
    qk_kernel<<<dim3(QCHUNKS, NHH, BB), 256, smemQK>>>(img, txt);
    pool_argmax_kernel<<<BH, 256>>>();
    upsample_mma_kernel<<<dim3(BH, 4), 256, smemGM>>>(img);
    gemm_gelu_res_kernel<<<dim3(HID / 128, SS / 128, BB), 256, smemGM>>>(img, out);
}

// round 16
// speedup vs baseline: 4.0563x; 1.2790x over previous
#include <cuda_runtime.h>
#include <cuda_bf16.h>
#include <cuda_fp16.h>
#include <math.h>
#include <cstdint>

#define BB    8
#define NHH   12
#define HID   768
#define HD    64
#define SS    1024
#define QQ    2048
#define EDGE  32
#define KPOOL 16
#define PDIM  17
#define TQ2   256
#define NCH   (QQ/TQ2)      /* 8 */
#define BH    (BB*NHH)      /* 96 */

// ---------------- scratch (static device arrays; no allocation) ----------------
__device__ float          g_partial[(size_t)BH * NCH * SS];      // per-chunk column-sum partials
__device__ int            g_row[BH];
__device__ int            g_col[BH];
__device__ __nv_bfloat16  g_uph[(size_t)BB * SS * HID];          // upsample result, bf16 hi
__device__ __nv_bfloat16  g_upl[(size_t)BB * SS * HID];          // upsample result, bf16 lo
__device__ __nv_bfloat16  g_WinTh[(size_t)HID * HID];            // W_in transposed [n][k], hi
__device__ __nv_bfloat16  g_WinTl[(size_t)HID * HID];            // W_in transposed [n][k], lo
__device__ __nv_bfloat16  g_WupTh[256 * HD];                     // W_up transposed [n][k], hi
__device__ __nv_bfloat16  g_WupTl[256 * HD];                     // W_up transposed [n][k], lo

// ============================ helpers =================================
__device__ __forceinline__ uint32_t smem_u32(const void* p) {
    uint32_t a;
    asm("{ .reg .u64 t; cvta.to.shared.u64 t, %1; cvt.u32.u64 %0, t; }" : "=r"(a) : "l"(p));
    return a;
}
#define SWZ(o) ((o) ^ (((o) >> 3) & 0x70))

__device__ __forceinline__ void ldsm4(uint32_t* r, uint32_t addr) {
    asm volatile("ldmatrix.sync.aligned.m8n8.x4.shared.b16 {%0,%1,%2,%3}, [%4];"
                 : "=r"(r[0]), "=r"(r[1]), "=r"(r[2]), "=r"(r[3]) : "r"(addr));
}
__device__ __forceinline__ void mma16816(float* d, const uint32_t* a, const uint32_t* b) {
    asm volatile("mma.sync.aligned.m16n8k16.row.col.f32.bf16.bf16.f32 "
                 "{%0,%1,%2,%3}, {%4,%5,%6,%7}, {%8,%9}, {%0,%1,%2,%3};"
                 : "+f"(d[0]), "+f"(d[1]), "+f"(d[2]), "+f"(d[3])
                 : "r"(a[0]), "r"(a[1]), "r"(a[2]), "r"(a[3]), "r"(b[0]), "r"(b[1]));
}
__device__ __forceinline__ void mma16816h(float* d, const uint32_t* a, const uint32_t* b) {
    asm volatile("mma.sync.aligned.m16n8k16.row.col.f32.f16.f16.f32 "
                 "{%0,%1,%2,%3}, {%4,%5,%6,%7}, {%8,%9}, {%0,%1,%2,%3};"
                 : "+f"(d[0]), "+f"(d[1]), "+f"(d[2]), "+f"(d[3])
                 : "r"(a[0]), "r"(a[1]), "r"(a[2]), "r"(a[3]), "r"(b[0]), "r"(b[1]));
}

// split one float4 into bf16 hi/lo pairs, store swizzled into 128B-row tiles
__device__ __forceinline__ void split_store(char* th, char* tl, int r, int seg, float4 v) {
    __nv_bfloat16 h0 = __float2bfloat16(v.x), h1 = __float2bfloat16(v.y);
    __nv_bfloat16 h2 = __float2bfloat16(v.z), h3 = __float2bfloat16(v.w);
    __nv_bfloat16 l0 = __float2bfloat16(v.x - __bfloat162float(h0));
    __nv_bfloat16 l1 = __float2bfloat16(v.y - __bfloat162float(h1));
    __nv_bfloat16 l2 = __float2bfloat16(v.z - __bfloat162float(h2));
    __nv_bfloat16 l3 = __float2bfloat16(v.w - __bfloat162float(h3));
    uint32_t sw = SWZ((uint32_t)(r * 128 + seg * 8));
    *(__nv_bfloat162*)(th + sw)     = __nv_bfloat162(h0, h1);
    *(__nv_bfloat162*)(th + sw + 4) = __nv_bfloat162(h2, h3);
    *(__nv_bfloat162*)(tl + sw)     = __nv_bfloat162(l0, l1);
    *(__nv_bfloat162*)(tl + sw + 4) = __nv_bfloat162(l2, l3);
}

// =========================================================================
// Kernel A: fused QK^T softmax column sums, single-term fp16 mma, K resident
// in smem. grid (8,12,8), 256 threads (8 warps = 4 m-blocks x 2 n-blocks).
// Pass 1: rowsums -> smem linv.  Pass 2: exp*linv column sums.
// smem: Qh 32KB | Kh 128KB (8 tiles) | scol 4KB | rowred 1KB  = 165KB
// =========================================================================
#define QK_KOFF   32768
#define QK_SCOL   163840
#define QK_ROWRED 167936
#define QK_SMEM   168960

__global__ __launch_bounds__(256)
void qk_kernel(const float* __restrict__ img, const float* __restrict__ txt)
{
    extern __shared__ char smem[];
    const uint32_t sb = smem_u32(smem);
    const uint32_t qh_b = sb, kh_b = sb + QK_KOFF;
    float* scol   = (float*)(smem + QK_SCOL);
    float* rowred = (float*)(smem + QK_ROWRED);

    const int chunk = blockIdx.x, h = blockIdx.y, b = blockIdx.z;
    const int tid = threadIdx.x, lane = tid & 31, wid = tid >> 5;
    const int warp_m = wid & 3, warp_n = wid >> 2;
    const int bh = b * NHH + h;
    const float SCALE = 0.18033688011112042f;   // log2(e)/8

    rowred[tid] = 0.f;

    // ---- load Q tile (pre-scaled) 256 rows x 64 k, fp16 swizzled ----
    {
        const float* qbase = txt + ((size_t)b * QQ + (size_t)chunk * TQ2) * HID + h * HD;
        #pragma unroll
        for (int it = 0; it < 16; it++) {
            int i = tid + it * 256;
            int r = i >> 4, seg = i & 15;
            float4 v = __ldg((const float4*)(qbase + (size_t)r * HID) + seg);
            __half2 h01 = __floats2half2_rn(v.x * SCALE, v.y * SCALE);
            __half2 h23 = __floats2half2_rn(v.z * SCALE, v.w * SCALE);
            uint32_t sw = SWZ((uint32_t)(r * 128 + seg * 8));
            *(__half2*)(smem + sw)     = h01;
            *(__half2*)(smem + sw + 4) = h23;
        }
    }
    // ---- load FULL K (1024 rows x 64 k) into 8 resident fp16 tiles ----
    {
        const float* kroot = img + (size_t)b * SS * HID + h * HD;
        #pragma unroll
        for (int it = 0; it < 64; it++) {
            int i = tid + it * 256;
            int r = i >> 4, seg = i & 15;
            float4 v = __ldg((const float4*)(kroot + (size_t)r * HID) + seg);
            __half2 h01 = __floats2half2_rn(v.x, v.y);
            __half2 h23 = __floats2half2_rn(v.z, v.w);
            uint32_t off = (uint32_t)(r >> 7) * 16384 + SWZ((uint32_t)((r & 127) * 128 + seg * 8));
            *(__half2*)(smem + QK_KOFF + off)     = h01;
            *(__half2*)(smem + QK_KOFF + off + 4) = h23;
        }
    }
    __syncthreads();

    // per-lane ldmatrix offsets
    const int a_row  = warp_m * 64 + (lane & 15);                    // + mt*16
    const int a_koff = (lane >> 4) * 16;                             // + ks*32
    const int b_row  = warp_n * 64 + ((lane >> 4) * 8) + (lane & 7); // + np*16
    const int b_koff = ((lane >> 3) & 1) * 16;                       // + ks*32

    float rs[8] = {0.f, 0.f, 0.f, 0.f, 0.f, 0.f, 0.f, 0.f};
    float lv[8];
    float* gpart = g_partial + ((size_t)bh * NCH + chunk) * SS;

    // ==================== PASS 1: rowsums ====================
    for (int st = 0; st < 8; st++) {
        const uint32_t kt = kh_b + st * 16384;
        float c[4][8][4];
        #pragma unroll
        for (int mt = 0; mt < 4; mt++)
            #pragma unroll
            for (int nt = 0; nt < 8; nt++)
                #pragma unroll
                for (int j = 0; j < 4; j++) c[mt][nt][j] = 0.f;

        #pragma unroll
        for (int ks = 0; ks < 4; ks++) {
            uint32_t af[4][4];
            #pragma unroll
            for (int mt = 0; mt < 4; mt++)
                ldsm4(af[mt], qh_b + SWZ((uint32_t)((a_row + mt * 16) * 128 + ks * 32 + a_koff)));
            #pragma unroll
            for (int np = 0; np < 4; np++) {
                uint32_t bf[4];
                ldsm4(bf, kt + SWZ((uint32_t)((b_row + np * 16) * 128 + ks * 32 + b_koff)));
                #pragma unroll
                for (int mt = 0; mt < 4; mt++) {
                    mma16816h(c[mt][np * 2],     af[mt], bf);
                    mma16816h(c[mt][np * 2 + 1], af[mt], bf + 2);
                }
            }
        }
        #pragma unroll
        for (int mt = 0; mt < 4; mt++) {
            float s0 = 0.f, s1 = 0.f;
            #pragma unroll
            for (int nt = 0; nt < 8; nt++) {
                s0 += exp2f(c[mt][nt][0]) + exp2f(c[mt][nt][1]);
                s1 += exp2f(c[mt][nt][2]) + exp2f(c[mt][nt][3]);
            }
            rs[mt * 2]     += s0;
            rs[mt * 2 + 1] += s1;
        }
    }

    // reduce rs over the 4-lane column group, build linv
    #pragma unroll
    for (int k = 0; k < 8; k++) {
        rs[k] += __shfl_xor_sync(0xFFFFFFFFu, rs[k], 1);
        rs[k] += __shfl_xor_sync(0xFFFFFFFFu, rs[k], 2);
    }
    if ((lane & 3) == 0) {
        #pragma unroll
        for (int k = 0; k < 8; k++) {
            int rl = warp_m * 64 + (k >> 1) * 16 + (k & 1) * 8 + (lane >> 2);
            atomicAdd(&rowred[rl], rs[k]);
        }
    }
    __syncthreads();
    rowred[tid] = 1.0f / rowred[tid];
    for (int i = tid; i < SS; i += 256) scol[i] = 0.f;
    __syncthreads();
    #pragma unroll
    for (int k = 0; k < 8; k++)
        lv[k] = rowred[warp_m * 64 + (k >> 1) * 16 + (k & 1) * 8 + (lane >> 2)];

    // ==================== PASS 2: column sums ====================
    for (int st = 0; st < 8; st++) {
        const uint32_t kt = kh_b + st * 16384;
        float c[4][8][4];
        #pragma unroll
        for (int mt = 0; mt < 4; mt++)
            #pragma unroll
            for (int nt = 0; nt < 8; nt++)
                #pragma unroll
                for (int j = 0; j < 4; j++) c[mt][nt][j] = 0.f;

        #pragma unroll
        for (int ks = 0; ks < 4; ks++) {
            uint32_t af[4][4];
            #pragma unroll
            for (int mt = 0; mt < 4; mt++)
                ldsm4(af[mt], qh_b + SWZ((uint32_t)((a_row + mt * 16) * 128 + ks * 32 + a_koff)));
            #pragma unroll
            for (int np = 0; np < 4; np++) {
                uint32_t bf[4];
                ldsm4(bf, kt + SWZ((uint32_t)((b_row + np * 16) * 128 + ks * 32 + b_koff)));
                #pragma unroll
                for (int mt = 0; mt < 4; mt++) {
                    mma16816h(c[mt][np * 2],     af[mt], bf);
                    mma16816h(c[mt][np * 2 + 1], af[mt], bf + 2);
                }
            }
        }

        #pragma unroll
        for (int nt = 0; nt < 8; nt++) {
            float v0 = 0.f, v1 = 0.f;
            #pragma unroll
            for (int mt = 0; mt < 4; mt++) {
                v0 += exp2f(c[mt][nt][0]) * lv[mt * 2] + exp2f(c[mt][nt][2]) * lv[mt * 2 + 1];
                v1 += exp2f(c[mt][nt][1]) * lv[mt * 2] + exp2f(c[mt][nt][3]) * lv[mt * 2 + 1];
            }
            v0 += __shfl_xor_sync(0xFFFFFFFFu, v0, 4);
            v0 += __shfl_xor_sync(0xFFFFFFFFu, v0, 8);
            v0 += __shfl_xor_sync(0xFFFFFFFFu, v0, 16);
            v1 += __shfl_xor_sync(0xFFFFFFFFu, v1, 4);
            v1 += __shfl_xor_sync(0xFFFFFFFFu, v1, 8);
            v1 += __shfl_xor_sync(0xFFFFFFFFu, v1, 16);
            if (lane < 4) {
                int col = st * 128 + warp_n * 64 + nt * 8 + lane * 2;
                atomicAdd(&scol[col], v0);
                atomicAdd(&scol[col + 1], v1);
            }
        }
    }

    __syncthreads();
    for (int i = tid; i < SS; i += 256) gpart[i] = scol[i];
}

// =========================================================================
// Kernel B: reduce partials, 16x16 pool (sums), argmax (first-index ties).
// =========================================================================
__global__ void pool_argmax_kernel()
{
    __shared__ float attn[SS];
    __shared__ float hsum[EDGE * PDIM];
    __shared__ float pooled[PDIM * PDIM];
    const int bh = blockIdx.x;
    const int tid = threadIdx.x;

    for (int s = tid; s < SS; s += 256) {
        float v = 0.f;
        #pragma unroll
        for (int c = 0; c < NCH; c++)
            v += g_partial[((size_t)bh * NCH + c) * SS + s];
        attn[s] = v;
    }
    __syncthreads();
    for (int t = tid; t < EDGE * PDIM; t += 256) {
        int r = t / PDIM, c = t % PDIM;
        float v = 0.f;
        #pragma unroll
        for (int j = 0; j < KPOOL; j++) v += attn[r * EDGE + c + j];
        hsum[t] = v;
    }
    __syncthreads();
    for (int t = tid; t < PDIM * PDIM; t += 256) {
        int r0 = t / PDIM, c = t % PDIM;
        float v = 0.f;
        #pragma unroll
        for (int r = 0; r < KPOOL; r++) v += hsum[(r0 + r) * PDIM + c];
        pooled[t] = v;
    }
    __syncthreads();
    if (tid == 0) {
        float best = -1e30f; int bi = 0;
        for (int t = 0; t < PDIM * PDIM; t++) {
            if (pooled[t] > best) { best = pooled[t]; bi = t; }
        }
        g_row[bh] = bi / PDIM;
        g_col[bh] = bi % PDIM;
    }
}

// =========================================================================
// Kernel P2: transpose + bf16-split W_up once: WupT[n][k] = Wup[k][n].
// =========================================================================
__global__ void wupT_kernel(const float* __restrict__ Wup)
{
    int idx = blockIdx.x * 256 + threadIdx.x;   // 64 x 256 = 16384
    int k = idx >> 8, n = idx & 255;
    float x = Wup[idx];
    __nv_bfloat16 hi = __float2bfloat16(x);
    g_WupTh[n * HD + k] = hi;
    g_WupTl[n * HD + k] = __float2bfloat16(x - __bfloat162float(hi));
}

// =========================================================================
// Kernel C: upsample as mma GEMM: region[256x64] @ WupT^T -> pixel-shuffled
// bf16 hi/lo. grid (96,4): bq = (rt<<1)|ct, 128x128x64 tile per block.
// =========================================================================
__global__ __launch_bounds__(256)
void upsample_mma_kernel(const float* __restrict__ img)
{
    extern __shared__ char smem[];
    char* Ah = smem;
    char* Al = smem + 16384;
    char* Bh = smem + 32768;
    char* Bl = smem + 49152;
    const uint32_t sb = smem_u32(smem);
    const uint32_t ah_b = sb, al_b = sb + 16384, bh_b = sb + 32768, bl_b = sb + 49152;

    const int bh = blockIdx.x, bq = blockIdx.y;
    const int rt = bq >> 1, ct = bq & 1;
    const int b = bh / NHH, h = bh % NHH;
    const int tid = threadIdx.x, lane = tid & 31, wid = tid >> 5;
    const int warp_m = wid & 3, warp_n = wid >> 2;
    const int row = g_row[bh], col = g_col[bh];

    // ---- A: 128 region tokens (coalesced 256B rows), split bf16 hi/lo ----
    #pragma unroll
    for (int it = 0; it < 8; it++) {
        int i = tid + it * 256;
        int r = i >> 4, seg = i & 15;
        int t = rt * 128 + r;
        int r2 = t >> 4, c2 = t & 15;
        const float* rp = img + ((size_t)b * SS + (size_t)(row + r2) * EDGE + (col + c2)) * HID + h * HD;
        float4 v = __ldg((const float4*)rp + seg);
        split_store(Ah, Al, r, seg, v);
    }
    // ---- B: 128 rows of WupT (pre-split bf16) ----
    #pragma unroll
    for (int it = 0; it < 4; it++) {
        int i = tid + it * 256;
        int r = i >> 3, seg = i & 7;
        uint32_t sw = SWZ((uint32_t)(r * 128 + seg * 16));
        size_t o = (size_t)(ct * 128 + r) * HD + seg * 8;
        *(uint4*)(Bh + sw) = *(const uint4*)(g_WupTh + o);
        *(uint4*)(Bl + sw) = *(const uint4*)(g_WupTl + o);
    }
    __syncthreads();

    const int a_row  = warp_m * 32 + (lane & 15);
    const int a_koff = (lane >> 4) * 16;
    const int b_row  = warp_n * 64 + ((lane >> 4) * 8) + (lane & 7);
    const int b_koff = ((lane >> 3) & 1) * 16;

    float c[2][8][4];
    #pragma unroll
    for (int mt = 0; mt < 2; mt++)
        #pragma unroll
        for (int nt = 0; nt < 8; nt++)
            #pragma unroll
            for (int j = 0; j < 4; j++) c[mt][nt][j] = 0.f;

    #pragma unroll
    for (int ks = 0; ks < 4; ks++) {
        uint32_t ah[2][4], al[2][4];
        #pragma unroll
        for (int mt = 0; mt < 2; mt++) {
            uint32_t byte = (uint32_t)((a_row + mt * 16) * 128 + ks * 32 + a_koff);
            ldsm4(ah[mt], ah_b + SWZ(byte));
            ldsm4(al[mt], al_b + SWZ(byte));
        }
        #pragma unroll
        for (int np = 0; np < 4; np++) {
            uint32_t bhf[4], blf[4];
            uint32_t byte = (uint32_t)((b_row + np * 16) * 128 + ks * 32 + b_koff);
            ldsm4(bhf, bh_b + SWZ(byte));
            ldsm4(blf, bl_b + SWZ(byte));
            #pragma unroll
            for (int mt = 0; mt < 2; mt++) {
                mma16816(c[mt][np * 2],     ah[mt], bhf);
                mma16816(c[mt][np * 2 + 1], ah[mt], bhf + 2);
                mma16816(c[mt][np * 2],     al[mt], bhf);
                mma16816(c[mt][np * 2 + 1], al[mt], bhf + 2);
                mma16816(c[mt][np * 2],     ah[mt], blf);
                mma16816(c[mt][np * 2 + 1], ah[mt], blf + 2);
            }
        }
    }

    // ---- epilogue: pixel-shuffle scatter, bf16 hi/lo pairs ----
    #pragma unroll
    for (int mt = 0; mt < 2; mt++) {
        #pragma unroll
        for (int nt = 0; nt < 8; nt++) {
            int col_local = warp_n * 64 + nt * 8 + (lane & 3) * 2;
            int co = ct * 128 + col_local;
            int dr = co >> 7, dc = (co >> 6) & 1, d = co & 63;
            #pragma unroll
            for (int half = 0; half < 2; half++) {
                int rl = warp_m * 32 + mt * 16 + (lane >> 2) + half * 8;
                int t = rt * 128 + rl;
                int r2 = t >> 4, c2 = t & 15;
                int pos = (2 * r2 + dr) * EDGE + (2 * c2 + dc);
                size_t o = ((size_t)b * SS + pos) * HID + h * HD + d;
                float x0 = c[mt][nt][half * 2], x1 = c[mt][nt][half * 2 + 1];
                __nv_bfloat16 h0 = __float2bfloat16(x0);
                __nv_bfloat16 h1 = __float2bfloat16(x1);
                __nv_bfloat16 l0 = __float2bfloat16(x0 - __bfloat162float(h0));
                __nv_bfloat16 l1 = __float2bfloat16(x1 - __bfloat162float(h1));
                *(__nv_bfloat162*)(g_uph + o) = __nv_bfloat162(h0, h1);
                *(__nv_bfloat162*)(g_upl + o) = __nv_bfloat162(l0, l1);
            }
        }
    }
}

// =========================================================================
// Kernel P: transpose + bf16-split W_in once:  WT[n][k] = W[k][n].
// =========================================================================
__global__ void winT_kernel(const float* __restrict__ W)
{
    __shared__ float t[32][33];
    const int n0 = blockIdx.x * 32, k0 = blockIdx.y * 32;
    const int tx = threadIdx.x, ty = threadIdx.y;
    for (int i = ty; i < 32; i += 8)
        t[i][tx] = W[(size_t)(k0 + i) * HID + n0 + tx];
    __syncthreads();
    for (int i = ty; i < 32; i += 8) {
        float x = t[tx][i];                 // = W[k0+tx][n0+i]
        __nv_bfloat16 hi = __float2bfloat16(x);
        size_t o = (size_t)(n0 + i) * HID + k0 + tx;
        g_WinTh[o] = hi;
        g_WinTl[o] = __float2bfloat16(x - __bfloat162float(hi));
    }
}

// =========================================================================
// Kernel D: out = residual + gelu_exact(up @ W_in), mma.sync 3-term split.
// grid (6,8,8), 256 threads, 128x128 tile, k-chunks of 64.
// =========================================================================
__device__ __forceinline__ float gelu_exact(float x)
{
    return 0.5f * x * (1.0f + erff(x * 0.70710678118654752440f));
}

__global__ __launch_bounds__(256, 2)
void gemm_gelu_res_kernel(const float* __restrict__ img, float* __restrict__ out)
{
    extern __shared__ char smem[];
    char* Ah = smem;
    char* Al = smem + 16384;
    char* Bh = smem + 32768;
    char* Bl = smem + 49152;
    const uint32_t sb = smem_u32(smem);
    const uint32_t ah_b = sb, al_b = sb + 16384, bh_b = sb + 32768, bl_b = sb + 49152;

    const int ct = blockIdx.x, rt = blockIdx.y, b = blockIdx.z;
    const int tid = threadIdx.x, lane = tid & 31, wid = tid >> 5;
    const int warp_m = wid & 3, warp_n = wid >> 2;
    const int row0 = rt * 128, col0 = ct * 128;

    const int a_row  = warp_m * 32 + (lane & 15);
    const int a_koff = (lane >> 4) * 16;
    const int b_row  = warp_n * 64 + ((lane >> 4) * 8) + (lane & 7);
    const int b_koff = ((lane >> 3) & 1) * 16;

    float c[2][8][4];
    #pragma unroll
    for (int mt = 0; mt < 2; mt++)
        #pragma unroll
        for (int nt = 0; nt < 8; nt++)
            #pragma unroll
            for (int j = 0; j < 4; j++) c[mt][nt][j] = 0.f;

    for (int kc = 0; kc < HID / 64; kc++) {
        __syncthreads();
        #pragma unroll
        for (int it = 0; it < 4; it++) {
            int i = tid + it * 256;
            int r = i >> 3, seg = i & 7;
            uint32_t sw = SWZ((uint32_t)(r * 128 + seg * 16));
            size_t ao = ((size_t)(b * SS + row0 + r)) * HID + kc * 64 + seg * 8;
            *(uint4*)(Ah + sw) = __ldg((const uint4*)(g_uph + ao));
            *(uint4*)(Al + sw) = __ldg((const uint4*)(g_upl + ao));
            size_t bo = ((size_t)(col0 + r)) * HID + kc * 64 + seg * 8;
            *(uint4*)(Bh + sw) = __ldg((const uint4*)(g_WinTh + bo));
            *(uint4*)(Bl + sw) = __ldg((const uint4*)(g_WinTl + bo));
        }
        __syncthreads();

        #pragma unroll
        for (int ks = 0; ks < 4; ks++) {
            uint32_t ah[2][4], al[2][4];
            #pragma unroll
            for (int mt = 0; mt < 2; mt++) {
                uint32_t byte = (uint32_t)((a_row + mt * 16) * 128 + ks * 32 + a_koff);
                ldsm4(ah[mt], ah_b + SWZ(byte));
                ldsm4(al[mt], al_b + SWZ(byte));
            }
            #pragma unroll
            for (int np = 0; np < 4; np++) {
                uint32_t bhf[4], blf[4];
                uint32_t byte = (uint32_t)((b_row + np * 16) * 128 + ks * 32 + b_koff);
                ldsm4(bhf, bh_b + SWZ(byte));
                ldsm4(blf, bl_b + SWZ(byte));
                #pragma unroll
                for (int mt = 0; mt < 2; mt++) {
                    mma16816(c[mt][np * 2],     ah[mt], bhf);
                    mma16816(c[mt][np * 2 + 1], ah[mt], bhf + 2);
                    mma16816(c[mt][np * 2],     al[mt], bhf);
                    mma16816(c[mt][np * 2 + 1], al[mt], bhf + 2);
                    mma16816(c[mt][np * 2],     ah[mt], blf);
                    mma16816(c[mt][np * 2 + 1], ah[mt], blf + 2);
                }
            }
        }
    }

    // epilogue: residual + gelu
    #pragma unroll
    for (int mt = 0; mt < 2; mt++) {
        int r0i = row0 + warp_m * 32 + mt * 16 + (lane >> 2);
        #pragma unroll
        for (int nt = 0; nt < 8; nt++) {
            int col = col0 + warp_n * 64 + nt * 8 + (lane & 3) * 2;
            {
                const float2 res = *(const float2*)(img + ((size_t)b * SS + r0i) * HID + col);
                float2 o;
                o.x = res.x + gelu_exact(c[mt][nt][0]);
                o.y = res.y + gelu_exact(c[mt][nt][1]);
                *(float2*)(out + ((size_t)b * SS + r0i) * HID + col) = o;
            }
            {
                const float2 res = *(const float2*)(img + ((size_t)b * SS + r0i + 8) * HID + col);
                float2 o;
                o.x = res.x + gelu_exact(c[mt][nt][2]);
                o.y = res.y + gelu_exact(c[mt][nt][3]);
                *(float2*)(out + ((size_t)b * SS + r0i + 8) * HID + col) = o;
            }
        }
    }
}

// =========================================================================
extern "C" void kernel_launch(void* const* d_in, const int* in_sizes, int n_in,
                              void* d_out, int out_size)
{
    const float* img = (const float*)d_in[0];   // [8,1024,768]
    const float* txt = (const float*)d_in[1];   // [8,2048,768]
    const float* Win = (const float*)d_in[2];   // [768,768]
    const float* Wup = (const float*)d_in[3];   // [64,256]
    float* out = (float*)d_out;                 // [8,1024,768]

    const int smemGM = 65536;
    cudaFuncSetAttribute(qk_kernel,            cudaFuncAttributeMaxDynamicSharedMemorySize, QK_SMEM);
    cudaFuncSetAttribute(gemm_gelu_res_kernel, cudaFuncAttributeMaxDynamicSharedMemorySize, smemGM);
    cudaFuncSetAttribute(upsample_mma_kernel,  cudaFuncAttributeMaxDynamicSharedMemorySize, smemGM);

    winT_kernel<<<dim3(HID / 32, HID / 32), dim3(32, 8)>>>(Win);
    wupT_kernel<<<64, 256>>>(Wup);
    qk_kernel<<<dim3(NCH, NHH, BB), 256, QK_SMEM>>>(img, txt);
    pool_argmax_kernel<<<BH, 256>>>();
    upsample_mma_kernel<<<dim3(BH, 4), 256, smemGM>>>(img);
    gemm_gelu_res_kernel<<<dim3(HID / 128, SS / 128, BB), 256, smemGM>>>(img, out);
}